// round 13
// baseline (speedup 1.0000x reference)
#include <cuda_runtime.h>
#include <cuda_fp16.h>
#include <math.h>
#include <stdint.h>

#define B_ 4
#define T_ 2048
#define DM_ 2048
#define H_ 16
#define KV_ 8
#define HD_ 128
#define G_ 2

// Scratch (no allocations allowed) — static device globals.
__device__ __half g_xh[B_*T_*DM_];
__device__ __half g_qr[B_*T_*H_*HD_];
__device__ __half g_kr[B_*T_*KV_*HD_];
__device__ __half g_vr[B_*T_*KV_*HD_];
__device__ __half g_qh[B_*T_*H_*HD_];
__device__ __half g_kh[B_*T_*KV_*HD_];
__device__ __half g_oh[B_*T_*H_*HD_];
__device__ __half g_wt[12*1024*1024];   // WqkvT [4096][2048], WoT [2048][2048]

// ---------------------------------------------------------------------------
// Helpers
// ---------------------------------------------------------------------------
__device__ __forceinline__ uint32_t h2u(__half2 h) { return *(uint32_t*)&h; }
__device__ __forceinline__ uint32_t pack2(float lo, float hi) {
    return h2u(__floats2half2_rn(lo, hi));
}
__device__ __forceinline__ float ex2(float x) {
    float r;
    asm("ex2.approx.f32 %0, %1;" : "=f"(r) : "f"(x));
    return r;
}

__device__ __forceinline__ void mma_f16(float c[4],
                                        uint32_t a0, uint32_t a1, uint32_t a2, uint32_t a3,
                                        uint32_t b0, uint32_t b1) {
    asm volatile(
        "mma.sync.aligned.m16n8k16.row.col.f32.f16.f16.f32 "
        "{%0,%1,%2,%3}, {%4,%5,%6,%7}, {%8,%9}, {%0,%1,%2,%3};"
        : "+f"(c[0]), "+f"(c[1]), "+f"(c[2]), "+f"(c[3])
        : "r"(a0), "r"(a1), "r"(a2), "r"(a3), "r"(b0), "r"(b1));
}

// ldmatrix x4 (non-trans): A-frags / B-frags from [row][k] tiles.
__device__ __forceinline__ void ldsm_x4(uint32_t* d, uint32_t addr) {
    asm volatile("ldmatrix.sync.aligned.m8n8.x4.shared.b16 {%0,%1,%2,%3}, [%4];"
                 : "=r"(d[0]), "=r"(d[1]), "=r"(d[2]), "=r"(d[3]) : "r"(addr));
}
// ldmatrix x4 trans: B-frags (Vᵀ) from row-major [k(s)][n(hd)] tiles.
__device__ __forceinline__ void ldsm_x4_t(uint32_t* d, uint32_t addr) {
    asm volatile("ldmatrix.sync.aligned.m8n8.x4.trans.shared.b16 {%0,%1,%2,%3}, [%4];"
                 : "=r"(d[0]), "=r"(d[1]), "=r"(d[2]), "=r"(d[3]) : "r"(addr));
}

__device__ __forceinline__ uint32_t smem_u32(const void* p) {
    uint32_t a;
    asm("{ .reg .u64 t; cvta.to.shared.u64 t, %1; cvt.u32.u64 %0, t; }" : "=r"(a) : "l"(p));
    return a;
}
__device__ __forceinline__ void cp16(uint32_t s, const void* g) {
    asm volatile("cp.async.ca.shared.global [%0], [%1], 16;" :: "r"(s), "l"(g));
}
#define CP_COMMIT() asm volatile("cp.async.commit_group;")
#define CP_WAIT1()  asm volatile("cp.async.wait_group 1;")

// ---------------------------------------------------------------------------
// Weight transpose + fp16 convert: W[K][N] -> WT[N][K] (half).
// ---------------------------------------------------------------------------
__global__ void transpose_cvt(const float* __restrict__ W, __half* __restrict__ WT,
                              int K, int N)
{
    __shared__ float t[32][33];
    int n0 = blockIdx.x * 32, k0 = blockIdx.y * 32;
    int tx = threadIdx.x & 31, ty = threadIdx.x >> 5;
    #pragma unroll
    for (int j = 0; j < 4; j++)
        t[ty + 8 * j][tx] = W[(size_t)(k0 + ty + 8 * j) * N + n0 + tx];
    __syncthreads();
    #pragma unroll
    for (int j = 0; j < 4; j++)
        WT[(size_t)(n0 + ty + 8 * j) * K + k0 + tx] = __float2half_rn(t[tx][ty + 8 * j]);
}

// fp32 -> fp16 bulk convert (8 elements/thread).
__global__ void cvt_half(const float* __restrict__ in, __half* __restrict__ out)
{
    size_t i = ((size_t)blockIdx.x * blockDim.x + threadIdx.x) * 8;
    float4 a = *(const float4*)&in[i];
    float4 b = *(const float4*)&in[i + 4];
    *(uint4*)&out[i] = make_uint4(pack2(a.x, a.y), pack2(a.z, a.w),
                                  pack2(b.x, b.y), pack2(b.z, b.w));
}

// ---------------------------------------------------------------------------
// All-fp16 pipelined GEMM: block 128x256, BK=64, cp.async 2-stage,
// 256 threads = 8 warps (2m x 4n of 64x64 tiles), m16n8k16, ldmatrix frags.
// If Cf != null: fp32 out (ldc=N). Else fused-QKV fp16 routing.
// ---------------------------------------------------------------------------
#define GST 72
#define GT_A (128 * GST)
#define GT_B (256 * GST)
#define GEMM_SMEM ((2 * (GT_A + GT_B)) * 2)   // 110592 bytes

__global__ __launch_bounds__(256, 1)
void gemm_f16h(const __half* __restrict__ A, const __half* __restrict__ WT,
               float* __restrict__ Cf,
               __half* __restrict__ Hq, __half* __restrict__ Hk, __half* __restrict__ Hv,
               int M, int N, int K)
{
    extern __shared__ __half gsm[];
    __half* As[2] = { gsm, gsm + GT_A };
    __half* Bs[2] = { gsm + 2 * GT_A, gsm + 2 * GT_A + GT_B };

    int tid  = threadIdx.x;
    int lane = tid & 31;
    int warp = tid >> 5;
    int qr = lane >> 2, ql = lane & 3;
    int row_off = lane & 15;
    int col_off = (lane >> 4) << 3;
    int wm = (warp & 1) * 64;
    int wn = (warp >> 1) * 64;
    int bm = blockIdx.y * 128, bn = blockIdx.x * 256;

    float acc[4][8][4] = {};   // warp tile 64x64
    const int NT = K / 64;

    #pragma unroll
    for (int p = 0; p < 4; p++) {
        int slot = p * 256 + tid;
        int r = slot >> 3, c8 = (slot & 7) << 3;
        cp16(smem_u32(&As[0][r * GST + c8]), &A[(size_t)(bm + r) * K + c8]);
    }
    #pragma unroll
    for (int p = 0; p < 8; p++) {
        int slot = p * 256 + tid;
        int r = slot >> 3, c8 = (slot & 7) << 3;
        cp16(smem_u32(&Bs[0][r * GST + c8]), &WT[(size_t)(bn + r) * K + c8]);
    }
    CP_COMMIT();

    for (int kt = 0; kt < NT; kt++) {
        int buf = kt & 1;
        if (kt + 1 < NT) {
            int nxt = buf ^ 1;
            int k0 = (kt + 1) * 64;
            #pragma unroll
            for (int p = 0; p < 4; p++) {
                int slot = p * 256 + tid;
                int r = slot >> 3, c8 = (slot & 7) << 3;
                cp16(smem_u32(&As[nxt][r * GST + c8]), &A[(size_t)(bm + r) * K + k0 + c8]);
            }
            #pragma unroll
            for (int p = 0; p < 8; p++) {
                int slot = p * 256 + tid;
                int r = slot >> 3, c8 = (slot & 7) << 3;
                cp16(smem_u32(&Bs[nxt][r * GST + c8]), &WT[(size_t)(bn + r) * K + k0 + c8]);
            }
        }
        CP_COMMIT();
        CP_WAIT1();
        __syncthreads();

        uint32_t a_base = smem_u32(As[buf]);
        uint32_t b_base = smem_u32(Bs[buf]);
        #pragma unroll
        for (int ks = 0; ks < 4; ks++) {
            int kc = ks * 16;
            uint32_t af[4][4];
            #pragma unroll
            for (int fm = 0; fm < 4; fm++)
                ldsm_x4(af[fm],
                        a_base + (((wm + fm * 16 + row_off) * GST) + kc + col_off) * 2);
            uint32_t bf[4][4];
            #pragma unroll
            for (int i = 0; i < 4; i++)
                ldsm_x4(bf[i],
                        b_base + (((wn + i * 16 + row_off) * GST) + kc + col_off) * 2);
            #pragma unroll
            for (int fn = 0; fn < 8; fn++) {
                uint32_t b0 = bf[fn >> 1][fn & 1];
                uint32_t b1 = bf[fn >> 1][2 + (fn & 1)];
                #pragma unroll
                for (int fm = 0; fm < 4; fm++)
                    mma_f16(acc[fm][fn], af[fm][0], af[fm][1], af[fm][2], af[fm][3], b0, b1);
            }
        }
        __syncthreads();
    }

    if (Cf) {
        #pragma unroll
        for (int fm = 0; fm < 4; fm++) {
            #pragma unroll
            for (int fn = 0; fn < 8; fn++) {
                int r = bm + wm + fm * 16 + qr;
                int c = bn + wn + fn * 8 + ql * 2;
                *(float2*)&Cf[(size_t)r * N + c]       = make_float2(acc[fm][fn][0], acc[fm][fn][1]);
                *(float2*)&Cf[(size_t)(r + 8) * N + c] = make_float2(acc[fm][fn][2], acc[fm][fn][3]);
            }
        }
    } else {
        __half* Hb; int ldc, cofs;
        if (bn < 2048)      { Hb = Hq; ldc = 2048; cofs = bn; }
        else if (bn < 3072) { Hb = Hk; ldc = 1024; cofs = bn - 2048; }
        else                { Hb = Hv; ldc = 1024; cofs = bn - 3072; }
        #pragma unroll
        for (int fm = 0; fm < 4; fm++) {
            #pragma unroll
            for (int fn = 0; fn < 8; fn++) {
                int r = bm + wm + fm * 16 + qr;
                int c = cofs + wn + fn * 8 + ql * 2;
                *(uint32_t*)&Hb[(size_t)r * ldc + c]       = pack2(acc[fm][fn][0], acc[fm][fn][1]);
                *(uint32_t*)&Hb[(size_t)(r + 8) * ldc + c] = pack2(acc[fm][fn][2], acc[fm][fn][3]);
            }
        }
    }
}

// ---------------------------------------------------------------------------
// Fused RMSNorm + interleaved RoPE; fp16 in/out. outscale folds softmax
// 1/sqrt(HD) and log2(e) for exp2-domain softmax (q only).
// ---------------------------------------------------------------------------
__global__ void rmsrope_h(const __half* __restrict__ in, __half* __restrict__ outh,
                          const float* __restrict__ gamma,
                          const float* __restrict__ cosT, const float* __restrict__ sinT,
                          int nheads, float outscale)
{
    int gid  = blockIdx.x * blockDim.x + threadIdx.x;
    int lane = gid & 31;
    int w    = gid >> 5;
    int t    = (w / nheads) % T_;
    uint2 raw = *(const uint2*)&in[(size_t)w * HD_ + lane * 4];
    float2 v01 = __half22float2(*(__half2*)&raw.x);
    float2 v23 = __half22float2(*(__half2*)&raw.y);
    float ss = v01.x * v01.x + v01.y * v01.y + v23.x * v23.x + v23.y * v23.y;
    #pragma unroll
    for (int off = 16; off; off >>= 1) ss += __shfl_xor_sync(0xffffffffu, ss, off);
    float r = rsqrtf(ss * (1.0f / HD_) + 1e-6f);
    float4 g = *(const float4*)&gamma[lane * 4];
    float hx = v01.x * r * g.x, hy = v01.y * r * g.y;
    float hz = v23.x * r * g.z, hw = v23.y * r * g.w;
    int ci = t * HD_ + lane * 4;
    float c0 = cosT[ci], s0 = sinT[ci], c1 = cosT[ci + 2], s1 = sinT[ci + 2];
    float ox = (hx * c0 - hy * s0) * outscale;
    float oy = (hy * c0 + hx * s0) * outscale;
    float oz = (hz * c1 - hw * s1) * outscale;
    float ow = (hw * c1 + hz * s1) * outscale;
    *(uint2*)&outh[(size_t)w * HD_ + lane * 4] = make_uint2(pack2(ox, oy), pack2(oz, ow));
}

// ---------------------------------------------------------------------------
// FP16 flash attention: 256 q-rows/CTA, 256 threads = 8 warps (32 rows each),
// 64-wide K/V tiles cp.async double-buffered, m16n8k16 QK^T and PV.
// The K-tile is split into two 32-col halves; phases are interleaved so
// softmax(half A) overlaps the tensor-pipe drain of S(half B), and
// softmax(half B) overlaps the drain of PV(half A):
//   S_A -> S_B -> softmax_A -> PV_A -> softmax_B -> PV_B
// P stays in registers (S accumulator layout == PV A-operand layout);
// V row-major, transposed on load via ldmatrix.trans.
// ---------------------------------------------------------------------------
#define AQ_ST 136
#define KBUF (64 * AQ_ST)
#define VBUF (64 * AQ_ST)
#define ATTN_SMEM ((256*AQ_ST + 2*KBUF + 2*VBUF) * 2)   // 139264 B

// Online softmax for one 32-col half: consumes s_h[2][4][4], updates m/l,
// rescales oa when the max moved, and emits P frags (pp/pq) in PV A-layout.
#define SOFTMAX_HALF(s_h, pp_h, pq_h)                                          \
    do {                                                                       \
        _Pragma("unroll")                                                      \
        for (int f = 0; f < 2; f++) {                                          \
            float rm1 = -1e30f, rm2 = -1e30f;                                  \
            _Pragma("unroll")                                                  \
            for (int nf = 0; nf < 4; nf++) {                                   \
                rm1 = fmaxf(rm1, fmaxf(s_h[f][nf][0], s_h[f][nf][1]));         \
                rm2 = fmaxf(rm2, fmaxf(s_h[f][nf][2], s_h[f][nf][3]));         \
            }                                                                  \
            _Pragma("unroll")                                                  \
            for (int off = 1; off <= 2; off <<= 1) {                           \
                rm1 = fmaxf(rm1, __shfl_xor_sync(0xffffffffu, rm1, off));      \
                rm2 = fmaxf(rm2, __shfl_xor_sync(0xffffffffu, rm2, off));      \
            }                                                                  \
            float m1o = m[f][0], m2o = m[f][1];                                \
            float nm1 = fmaxf(m1o, rm1), nm2 = fmaxf(m2o, rm2);                \
            float rs1 = 0.f, rs2 = 0.f;                                        \
            _Pragma("unroll")                                                  \
            for (int nf = 0; nf < 4; nf++) {                                   \
                float p0 = ex2(s_h[f][nf][0] - nm1);                           \
                float p1 = ex2(s_h[f][nf][1] - nm1);                           \
                float p2 = ex2(s_h[f][nf][2] - nm2);                           \
                float p3 = ex2(s_h[f][nf][3] - nm2);                           \
                rs1 += p0 + p1; rs2 += p2 + p3;                                \
                pp_h[f][nf] = pack2(p0, p1);                                   \
                pq_h[f][nf] = pack2(p2, p3);                                   \
            }                                                                  \
            _Pragma("unroll")                                                  \
            for (int off = 1; off <= 2; off <<= 1) {                           \
                rs1 += __shfl_xor_sync(0xffffffffu, rs1, off);                 \
                rs2 += __shfl_xor_sync(0xffffffffu, rs2, off);                 \
            }                                                                  \
            float corr1 = ex2(m1o - nm1), corr2 = ex2(m2o - nm2);              \
            l[f][0] = l[f][0] * corr1 + rs1; m[f][0] = nm1;                    \
            l[f][1] = l[f][1] * corr2 + rs2; m[f][1] = nm2;                    \
            if (nm1 > m1o || nm2 > m2o) {                                      \
                _Pragma("unroll")                                              \
                for (int nf = 0; nf < 16; nf++) {                              \
                    oa[f][nf][0] *= corr1; oa[f][nf][1] *= corr1;              \
                    oa[f][nf][2] *= corr2; oa[f][nf][3] *= corr2;              \
                }                                                              \
            }                                                                  \
        }                                                                      \
    } while (0)

// PV for one half: k16 steps j = 2h, 2h+1 over s-rows [32h, 32h+32).
#define PV_HALF(h, pp_h, pq_h)                                                 \
    do {                                                                       \
        _Pragma("unroll")                                                      \
        for (int jl = 0; jl < 2; jl++) {                                       \
            int kc = ((h) * 2 + jl) * 16;                                      \
            uint32_t vb[8][4];                                                 \
            _Pragma("unroll")                                                  \
            for (int i = 0; i < 8; i++)                                        \
                ldsm_x4_t(vb[i],                                               \
                          vs_base + (((kc + row_off) * AQ_ST) + i * 16 + col_off) * 2); \
            _Pragma("unroll")                                                  \
            for (int nf = 0; nf < 16; nf++) {                                  \
                uint32_t b0 = vb[nf >> 1][2 * (nf & 1)];                       \
                uint32_t b1 = vb[nf >> 1][2 * (nf & 1) + 1];                   \
                _Pragma("unroll")                                              \
                for (int f = 0; f < 2; f++)                                    \
                    mma_f16(oa[f][nf], pp_h[f][2 * jl], pq_h[f][2 * jl],       \
                            pp_h[f][2 * jl + 1], pq_h[f][2 * jl + 1], b0, b1); \
            }                                                                  \
        }                                                                      \
    } while (0)

__global__ __launch_bounds__(256, 1)
void attn_f16(const __half* __restrict__ qh, const __half* __restrict__ kh,
              const __half* __restrict__ vr, __half* __restrict__ oh)
{
    extern __shared__ __half hsm[];
    __half* qs = hsm;                       // 256 x 136
    __half* ks = qs + 256 * AQ_ST;          // 2 x (64 x 136)
    __half* vs = ks + 2 * KBUF;             // 2 x (64 x 136), row-major [s][hd]

    int b = blockIdx.z, h = blockIdx.y;
    int kvh = h / G_;
    int t0 = blockIdx.x * 256;
    int tid = threadIdx.x, lane = tid & 31, warp = tid >> 5;
    int qr = lane >> 2;
    int ql = lane & 3;
    int row_off = lane & 15;
    int col_off = (lane >> 4) << 3;
    int r0w = warp * 32;

    const __half* kbase = kh + ((size_t)(b * T_) * KV_ + kvh) * HD_;
    const __half* vbase = vr + ((size_t)(b * T_) * KV_ + kvh) * HD_;

    // Stage Q (256x128) + K/V tile 0.
    #pragma unroll
    for (int p = 0; p < 16; p++) {
        int slot = p * 256 + tid;
        int row = slot >> 4, c8 = (slot & 15) << 3;
        cp16(smem_u32(&qs[row * AQ_ST + c8]),
             &qh[((size_t)(b * T_ + t0 + row) * H_ + h) * HD_ + c8]);
    }
    #pragma unroll
    for (int p = 0; p < 4; p++) {
        int slot = p * 256 + tid;
        int row = slot >> 4, c8 = (slot & 15) << 3;
        cp16(smem_u32(&ks[row * AQ_ST + c8]), &kbase[(size_t)row * (KV_ * HD_) + c8]);
    }
    #pragma unroll
    for (int p = 0; p < 4; p++) {
        int slot = p * 256 + tid;
        int row = slot >> 4, c8 = (slot & 15) << 3;
        cp16(smem_u32(&vs[row * AQ_ST + c8]), &vbase[(size_t)row * (KV_ * HD_) + c8]);
    }
    CP_COMMIT();

    float m[2][2] = {{-1e30f, -1e30f}, {-1e30f, -1e30f}};
    float l[2][2] = {};
    float oa[2][16][4] = {};
    uint32_t qs_base = smem_u32(qs);

    const int NT = T_ / 64;
    for (int kt = 0; kt < NT; kt++) {
        int buf = kt & 1;
        if (kt + 1 < NT) {
            int nxt = buf ^ 1;
            int s0g = (kt + 1) * 64;
            #pragma unroll
            for (int p = 0; p < 4; p++) {
                int slot = p * 256 + tid;
                int row = slot >> 4, c8 = (slot & 15) << 3;
                cp16(smem_u32(&ks[nxt * KBUF + row * AQ_ST + c8]),
                     &kbase[(size_t)(s0g + row) * (KV_ * HD_) + c8]);
            }
            #pragma unroll
            for (int p = 0; p < 4; p++) {
                int slot = p * 256 + tid;
                int row = slot >> 4, c8 = (slot & 15) << 3;
                cp16(smem_u32(&vs[nxt * VBUF + row * AQ_ST + c8]),
                     &vbase[(size_t)(s0g + row) * (KV_ * HD_) + c8]);
            }
        }
        CP_COMMIT();
        CP_WAIT1();
        __syncthreads();

        uint32_t ks_base = smem_u32(ks + buf * KBUF);
        uint32_t vs_base = smem_u32(vs + buf * VBUF);

        // S_A: Q @ K[0:32]^T  (cols 0..31)
        float sA[2][4][4] = {};
        #pragma unroll
        for (int j = 0; j < 8; j++) {
            int kc = j * 16;
            uint32_t aq[2][4];
            #pragma unroll
            for (int f = 0; f < 2; f++)
                ldsm_x4(aq[f],
                        qs_base + (((r0w + f * 16 + row_off) * AQ_ST) + kc + col_off) * 2);
            uint32_t kb[2][4];
            #pragma unroll
            for (int i = 0; i < 2; i++)
                ldsm_x4(kb[i],
                        ks_base + (((i * 16 + row_off) * AQ_ST) + kc + col_off) * 2);
            #pragma unroll
            for (int nf = 0; nf < 4; nf++) {
                uint32_t b0 = kb[nf >> 1][nf & 1];
                uint32_t b1 = kb[nf >> 1][2 + (nf & 1)];
                #pragma unroll
                for (int f = 0; f < 2; f++)
                    mma_f16(sA[f][nf], aq[f][0], aq[f][1], aq[f][2], aq[f][3], b0, b1);
            }
        }

        // S_B: Q @ K[32:64]^T (cols 32..63) — independent of softmax_A, so the
        // tensor pipe drains these while softmax_A runs on MUFU/ALU below.
        float sB[2][4][4] = {};
        #pragma unroll
        for (int j = 0; j < 8; j++) {
            int kc = j * 16;
            uint32_t aq[2][4];
            #pragma unroll
            for (int f = 0; f < 2; f++)
                ldsm_x4(aq[f],
                        qs_base + (((r0w + f * 16 + row_off) * AQ_ST) + kc + col_off) * 2);
            uint32_t kb[2][4];
            #pragma unroll
            for (int i = 0; i < 2; i++)
                ldsm_x4(kb[i],
                        ks_base + (((32 + i * 16 + row_off) * AQ_ST) + kc + col_off) * 2);
            #pragma unroll
            for (int nf = 0; nf < 4; nf++) {
                uint32_t b0 = kb[nf >> 1][nf & 1];
                uint32_t b1 = kb[nf >> 1][2 + (nf & 1)];
                #pragma unroll
                for (int f = 0; f < 2; f++)
                    mma_f16(sB[f][nf], aq[f][0], aq[f][1], aq[f][2], aq[f][3], b0, b1);
            }
        }

        // softmax_A (overlaps S_B drain), then PV_A, then softmax_B (overlaps
        // PV_A drain), then PV_B.
        uint32_t ppA[2][4], pqA[2][4];
        SOFTMAX_HALF(sA, ppA, pqA);
        PV_HALF(0, ppA, pqA);

        uint32_t ppB[2][4], pqB[2][4];
        SOFTMAX_HALF(sB, ppB, pqB);
        PV_HALF(1, ppB, pqB);

        __syncthreads();  // compute done before next iter's cp.async overwrites
    }

    #pragma unroll
    for (int f = 0; f < 2; f++) {
        float inv1 = 1.0f / l[f][0], inv2 = 1.0f / l[f][1];
        int rr = r0w + f * 16 + qr;
        size_t base1 = ((size_t)(b * T_ + t0 + rr) * H_ + h) * HD_;
        size_t base2 = ((size_t)(b * T_ + t0 + rr + 8) * H_ + h) * HD_;
        #pragma unroll
        for (int nf = 0; nf < 16; nf++) {
            int c = nf * 8 + ql * 2;
            *(uint32_t*)&oh[base1 + c] = pack2(oa[f][nf][0] * inv1, oa[f][nf][1] * inv1);
            *(uint32_t*)&oh[base2 + c] = pack2(oa[f][nf][2] * inv2, oa[f][nf][3] * inv2);
        }
    }
}

// ---------------------------------------------------------------------------
// Launch
// ---------------------------------------------------------------------------
extern "C" void kernel_launch(void* const* d_in, const int* in_sizes, int n_in,
                              void* d_out, int out_size)
{
    const float* x    = (const float*)d_in[0];
    const float* cosT = (const float*)d_in[1];
    const float* sinT = (const float*)d_in[2];
    const float* Wq   = (const float*)d_in[3];
    const float* Wk   = (const float*)d_in[4];
    const float* Wv   = (const float*)d_in[5];
    const float* Wo   = (const float*)d_in[6];
    const float* qg   = (const float*)d_in[7];
    const float* kg   = (const float*)d_in[8];

    __half *xh, *qr, *kr, *vr, *qh, *kh, *oh, *wt;
    cudaGetSymbolAddress((void**)&xh, g_xh);
    cudaGetSymbolAddress((void**)&qr, g_qr);
    cudaGetSymbolAddress((void**)&kr, g_kr);
    cudaGetSymbolAddress((void**)&vr, g_vr);
    cudaGetSymbolAddress((void**)&qh, g_qh);
    cudaGetSymbolAddress((void**)&kh, g_kh);
    cudaGetSymbolAddress((void**)&oh, g_oh);
    cudaGetSymbolAddress((void**)&wt, g_wt);

    __half* WqkvT = wt;                      // [4096][2048]
    __half* WoT   = wt + 8 * 1024 * 1024;    // [2048][2048]

    const int M = B_ * T_;  // 8192

    transpose_cvt<<<dim3(2048/32, 2048/32), 256>>>(Wq, WqkvT, DM_, 2048);
    transpose_cvt<<<dim3(1024/32, 2048/32), 256>>>(Wk, WqkvT + 2048ull*2048, DM_, 1024);
    transpose_cvt<<<dim3(1024/32, 2048/32), 256>>>(Wv, WqkvT + 3072ull*2048, DM_, 1024);
    transpose_cvt<<<dim3(2048/32, 2048/32), 256>>>(Wo, WoT, H_*HD_, 2048);
    cvt_half<<<(M * DM_) / (256 * 8), 256>>>(x, xh);

    cudaFuncSetAttribute(gemm_f16h, cudaFuncAttributeMaxDynamicSharedMemorySize, GEMM_SMEM);
    gemm_f16h<<<dim3(4096/256, M/128), 256, GEMM_SMEM>>>(xh, WqkvT, nullptr, qr, kr, vr,
                                                         M, 4096, DM_);

    const float qscale = 0.0883883476483184405f * 1.4426950408889634f;
    rmsrope_h<<<(M * H_) / 8, 256>>>(qr, qh, qg, cosT, sinT, H_, qscale);
    rmsrope_h<<<(M * KV_) / 8, 256>>>(kr, kh, kg, cosT, sinT, KV_, 1.0f);

    cudaFuncSetAttribute(attn_f16, cudaFuncAttributeMaxDynamicSharedMemorySize, ATTN_SMEM);
    attn_f16<<<dim3(T_ / 256, H_, B_), 256, ATTN_SMEM>>>(qh, kh, vr, oh);

    gemm_f16h<<<dim3(DM_/256, M/128), 256, GEMM_SMEM>>>(oh, WoT, (float*)d_out,
                                                        nullptr, nullptr, nullptr,
                                                        M, DM_, DM_);
}

// round 14
// speedup vs baseline: 1.0084x; 1.0084x over previous
#include <cuda_runtime.h>
#include <cuda_fp16.h>
#include <math.h>
#include <stdint.h>

#define B_ 4
#define T_ 2048
#define DM_ 2048
#define H_ 16
#define KV_ 8
#define HD_ 128
#define G_ 2

// Scratch (no allocations allowed) — static device globals.
__device__ __half g_xh[B_*T_*DM_];
__device__ __half g_qr[B_*T_*H_*HD_];
__device__ __half g_kr[B_*T_*KV_*HD_];
__device__ __half g_vr[B_*T_*KV_*HD_];
__device__ __half g_qh[B_*T_*H_*HD_];
__device__ __half g_kh[B_*T_*KV_*HD_];
__device__ __half g_oh[B_*T_*H_*HD_];
__device__ __half g_wt[12*1024*1024];   // WqkvT [4096][2048], WoT [2048][2048]

// ---------------------------------------------------------------------------
// Helpers
// ---------------------------------------------------------------------------
__device__ __forceinline__ uint32_t h2u(__half2 h) { return *(uint32_t*)&h; }
__device__ __forceinline__ uint32_t pack2(float lo, float hi) {
    return h2u(__floats2half2_rn(lo, hi));
}
__device__ __forceinline__ float ex2(float x) {
    float r;
    asm("ex2.approx.f32 %0, %1;" : "=f"(r) : "f"(x));
    return r;
}

__device__ __forceinline__ void mma_f16(float c[4],
                                        uint32_t a0, uint32_t a1, uint32_t a2, uint32_t a3,
                                        uint32_t b0, uint32_t b1) {
    asm volatile(
        "mma.sync.aligned.m16n8k16.row.col.f32.f16.f16.f32 "
        "{%0,%1,%2,%3}, {%4,%5,%6,%7}, {%8,%9}, {%0,%1,%2,%3};"
        : "+f"(c[0]), "+f"(c[1]), "+f"(c[2]), "+f"(c[3])
        : "r"(a0), "r"(a1), "r"(a2), "r"(a3), "r"(b0), "r"(b1));
}

// ldmatrix x4 (non-trans): A-frags / B-frags from [row][k] tiles.
__device__ __forceinline__ void ldsm_x4(uint32_t* d, uint32_t addr) {
    asm volatile("ldmatrix.sync.aligned.m8n8.x4.shared.b16 {%0,%1,%2,%3}, [%4];"
                 : "=r"(d[0]), "=r"(d[1]), "=r"(d[2]), "=r"(d[3]) : "r"(addr));
}
// ldmatrix x4 trans: B-frags (Vᵀ) from row-major [k(s)][n(hd)] tiles.
__device__ __forceinline__ void ldsm_x4_t(uint32_t* d, uint32_t addr) {
    asm volatile("ldmatrix.sync.aligned.m8n8.x4.trans.shared.b16 {%0,%1,%2,%3}, [%4];"
                 : "=r"(d[0]), "=r"(d[1]), "=r"(d[2]), "=r"(d[3]) : "r"(addr));
}

__device__ __forceinline__ uint32_t smem_u32(const void* p) {
    uint32_t a;
    asm("{ .reg .u64 t; cvta.to.shared.u64 t, %1; cvt.u32.u64 %0, t; }" : "=r"(a) : "l"(p));
    return a;
}
__device__ __forceinline__ void cp16(uint32_t s, const void* g) {
    asm volatile("cp.async.ca.shared.global [%0], [%1], 16;" :: "r"(s), "l"(g));
}
#define CP_COMMIT() asm volatile("cp.async.commit_group;")
#define CP_WAIT1()  asm volatile("cp.async.wait_group 1;")

// ---------------------------------------------------------------------------
// Weight transpose + fp16 convert: W[K][N] -> WT[N][K] (half).
// ---------------------------------------------------------------------------
__global__ void transpose_cvt(const float* __restrict__ W, __half* __restrict__ WT,
                              int K, int N)
{
    __shared__ float t[32][33];
    int n0 = blockIdx.x * 32, k0 = blockIdx.y * 32;
    int tx = threadIdx.x & 31, ty = threadIdx.x >> 5;
    #pragma unroll
    for (int j = 0; j < 4; j++)
        t[ty + 8 * j][tx] = W[(size_t)(k0 + ty + 8 * j) * N + n0 + tx];
    __syncthreads();
    #pragma unroll
    for (int j = 0; j < 4; j++)
        WT[(size_t)(n0 + ty + 8 * j) * K + k0 + tx] = __float2half_rn(t[tx][ty + 8 * j]);
}

// fp32 -> fp16 bulk convert (8 elements/thread).
__global__ void cvt_half(const float* __restrict__ in, __half* __restrict__ out)
{
    size_t i = ((size_t)blockIdx.x * blockDim.x + threadIdx.x) * 8;
    float4 a = *(const float4*)&in[i];
    float4 b = *(const float4*)&in[i + 4];
    *(uint4*)&out[i] = make_uint4(pack2(a.x, a.y), pack2(a.z, a.w),
                                  pack2(b.x, b.y), pack2(b.z, b.w));
}

// ---------------------------------------------------------------------------
// All-fp16 pipelined GEMM: block 128x256, BK=64, cp.async 2-stage,
// 256 threads = 8 warps (2m x 4n of 64x64 tiles), m16n8k16, ldmatrix frags.
// If Cf != null: fp32 out (ldc=N). Else fused-QKV fp16 routing.
// ---------------------------------------------------------------------------
#define GST 72
#define GT_A (128 * GST)
#define GT_B (256 * GST)
#define GEMM_SMEM ((2 * (GT_A + GT_B)) * 2)   // 110592 bytes

__global__ __launch_bounds__(256, 1)
void gemm_f16h(const __half* __restrict__ A, const __half* __restrict__ WT,
               float* __restrict__ Cf,
               __half* __restrict__ Hq, __half* __restrict__ Hk, __half* __restrict__ Hv,
               int M, int N, int K)
{
    extern __shared__ __half gsm[];
    __half* As[2] = { gsm, gsm + GT_A };
    __half* Bs[2] = { gsm + 2 * GT_A, gsm + 2 * GT_A + GT_B };

    int tid  = threadIdx.x;
    int lane = tid & 31;
    int warp = tid >> 5;
    int qr = lane >> 2, ql = lane & 3;
    int row_off = lane & 15;
    int col_off = (lane >> 4) << 3;
    int wm = (warp & 1) * 64;
    int wn = (warp >> 1) * 64;
    int bm = blockIdx.y * 128, bn = blockIdx.x * 256;

    float acc[4][8][4] = {};   // warp tile 64x64
    const int NT = K / 64;

    #pragma unroll
    for (int p = 0; p < 4; p++) {
        int slot = p * 256 + tid;
        int r = slot >> 3, c8 = (slot & 7) << 3;
        cp16(smem_u32(&As[0][r * GST + c8]), &A[(size_t)(bm + r) * K + c8]);
    }
    #pragma unroll
    for (int p = 0; p < 8; p++) {
        int slot = p * 256 + tid;
        int r = slot >> 3, c8 = (slot & 7) << 3;
        cp16(smem_u32(&Bs[0][r * GST + c8]), &WT[(size_t)(bn + r) * K + c8]);
    }
    CP_COMMIT();

    for (int kt = 0; kt < NT; kt++) {
        int buf = kt & 1;
        if (kt + 1 < NT) {
            int nxt = buf ^ 1;
            int k0 = (kt + 1) * 64;
            #pragma unroll
            for (int p = 0; p < 4; p++) {
                int slot = p * 256 + tid;
                int r = slot >> 3, c8 = (slot & 7) << 3;
                cp16(smem_u32(&As[nxt][r * GST + c8]), &A[(size_t)(bm + r) * K + k0 + c8]);
            }
            #pragma unroll
            for (int p = 0; p < 8; p++) {
                int slot = p * 256 + tid;
                int r = slot >> 3, c8 = (slot & 7) << 3;
                cp16(smem_u32(&Bs[nxt][r * GST + c8]), &WT[(size_t)(bn + r) * K + k0 + c8]);
            }
        }
        CP_COMMIT();
        CP_WAIT1();
        __syncthreads();

        uint32_t a_base = smem_u32(As[buf]);
        uint32_t b_base = smem_u32(Bs[buf]);
        #pragma unroll
        for (int ks = 0; ks < 4; ks++) {
            int kc = ks * 16;
            uint32_t af[4][4];
            #pragma unroll
            for (int fm = 0; fm < 4; fm++)
                ldsm_x4(af[fm],
                        a_base + (((wm + fm * 16 + row_off) * GST) + kc + col_off) * 2);
            uint32_t bf[4][4];
            #pragma unroll
            for (int i = 0; i < 4; i++)
                ldsm_x4(bf[i],
                        b_base + (((wn + i * 16 + row_off) * GST) + kc + col_off) * 2);
            #pragma unroll
            for (int fn = 0; fn < 8; fn++) {
                uint32_t b0 = bf[fn >> 1][fn & 1];
                uint32_t b1 = bf[fn >> 1][2 + (fn & 1)];
                #pragma unroll
                for (int fm = 0; fm < 4; fm++)
                    mma_f16(acc[fm][fn], af[fm][0], af[fm][1], af[fm][2], af[fm][3], b0, b1);
            }
        }
        __syncthreads();
    }

    if (Cf) {
        #pragma unroll
        for (int fm = 0; fm < 4; fm++) {
            #pragma unroll
            for (int fn = 0; fn < 8; fn++) {
                int r = bm + wm + fm * 16 + qr;
                int c = bn + wn + fn * 8 + ql * 2;
                *(float2*)&Cf[(size_t)r * N + c]       = make_float2(acc[fm][fn][0], acc[fm][fn][1]);
                *(float2*)&Cf[(size_t)(r + 8) * N + c] = make_float2(acc[fm][fn][2], acc[fm][fn][3]);
            }
        }
    } else {
        __half* Hb; int ldc, cofs;
        if (bn < 2048)      { Hb = Hq; ldc = 2048; cofs = bn; }
        else if (bn < 3072) { Hb = Hk; ldc = 1024; cofs = bn - 2048; }
        else                { Hb = Hv; ldc = 1024; cofs = bn - 3072; }
        #pragma unroll
        for (int fm = 0; fm < 4; fm++) {
            #pragma unroll
            for (int fn = 0; fn < 8; fn++) {
                int r = bm + wm + fm * 16 + qr;
                int c = cofs + wn + fn * 8 + ql * 2;
                *(uint32_t*)&Hb[(size_t)r * ldc + c]       = pack2(acc[fm][fn][0], acc[fm][fn][1]);
                *(uint32_t*)&Hb[(size_t)(r + 8) * ldc + c] = pack2(acc[fm][fn][2], acc[fm][fn][3]);
            }
        }
    }
}

// ---------------------------------------------------------------------------
// Fused RMSNorm + interleaved RoPE; fp16 in/out. outscale folds softmax
// 1/sqrt(HD) and log2(e) for exp2-domain softmax (q only).
// ---------------------------------------------------------------------------
__global__ void rmsrope_h(const __half* __restrict__ in, __half* __restrict__ outh,
                          const float* __restrict__ gamma,
                          const float* __restrict__ cosT, const float* __restrict__ sinT,
                          int nheads, float outscale)
{
    int gid  = blockIdx.x * blockDim.x + threadIdx.x;
    int lane = gid & 31;
    int w    = gid >> 5;
    int t    = (w / nheads) % T_;
    uint2 raw = *(const uint2*)&in[(size_t)w * HD_ + lane * 4];
    float2 v01 = __half22float2(*(__half2*)&raw.x);
    float2 v23 = __half22float2(*(__half2*)&raw.y);
    float ss = v01.x * v01.x + v01.y * v01.y + v23.x * v23.x + v23.y * v23.y;
    #pragma unroll
    for (int off = 16; off; off >>= 1) ss += __shfl_xor_sync(0xffffffffu, ss, off);
    float r = rsqrtf(ss * (1.0f / HD_) + 1e-6f);
    float4 g = *(const float4*)&gamma[lane * 4];
    float hx = v01.x * r * g.x, hy = v01.y * r * g.y;
    float hz = v23.x * r * g.z, hw = v23.y * r * g.w;
    int ci = t * HD_ + lane * 4;
    float c0 = cosT[ci], s0 = sinT[ci], c1 = cosT[ci + 2], s1 = sinT[ci + 2];
    float ox = (hx * c0 - hy * s0) * outscale;
    float oy = (hy * c0 + hx * s0) * outscale;
    float oz = (hz * c1 - hw * s1) * outscale;
    float ow = (hw * c1 + hz * s1) * outscale;
    *(uint2*)&outh[(size_t)w * HD_ + lane * 4] = make_uint2(pack2(ox, oy), pack2(oz, ow));
}

// ---------------------------------------------------------------------------
// FP16 flash attention: 128 q-rows/CTA, 128 threads = 4 warps (32 rows each),
// 2 CTAs/SM for cross-CTA latency hiding + fine-grained wave balance.
// 64-wide K/V tiles cp.async double-buffered, m16n8k16 QK^T and PV.
// V row-major, transposed on load via ldmatrix.trans; V frags for j=0
// prefetched ahead of the softmax; P stays in registers.
// ---------------------------------------------------------------------------
#define AQ_ST 136
#define KBUF (64 * AQ_ST)
#define VBUF (64 * AQ_ST)
#define ATTN_SMEM ((128*AQ_ST + 2*KBUF + 2*VBUF) * 2)   // 104448 B -> 2 CTA/SM

__global__ __launch_bounds__(128, 2)
void attn_f16(const __half* __restrict__ qh, const __half* __restrict__ kh,
              const __half* __restrict__ vr, __half* __restrict__ oh)
{
    extern __shared__ __half hsm[];
    __half* qs = hsm;                       // 128 x 136
    __half* ks = qs + 128 * AQ_ST;          // 2 x (64 x 136)
    __half* vs = ks + 2 * KBUF;             // 2 x (64 x 136), row-major [s][hd]

    int b = blockIdx.z, h = blockIdx.y;
    int kvh = h / G_;
    int t0 = blockIdx.x * 128;
    int tid = threadIdx.x, lane = tid & 31, warp = tid >> 5;
    int qr = lane >> 2;
    int ql = lane & 3;
    int row_off = lane & 15;
    int col_off = (lane >> 4) << 3;
    int r0w = warp * 32;

    const __half* kbase = kh + ((size_t)(b * T_) * KV_ + kvh) * HD_;
    const __half* vbase = vr + ((size_t)(b * T_) * KV_ + kvh) * HD_;

    // Stage Q (128x128) + K/V tile 0.  (128 threads)
    #pragma unroll
    for (int p = 0; p < 16; p++) {
        int slot = p * 128 + tid;
        int row = slot >> 4, c8 = (slot & 15) << 3;
        cp16(smem_u32(&qs[row * AQ_ST + c8]),
             &qh[((size_t)(b * T_ + t0 + row) * H_ + h) * HD_ + c8]);
    }
    #pragma unroll
    for (int p = 0; p < 8; p++) {
        int slot = p * 128 + tid;
        int row = slot >> 4, c8 = (slot & 15) << 3;
        cp16(smem_u32(&ks[row * AQ_ST + c8]), &kbase[(size_t)row * (KV_ * HD_) + c8]);
    }
    #pragma unroll
    for (int p = 0; p < 8; p++) {
        int slot = p * 128 + tid;
        int row = slot >> 4, c8 = (slot & 15) << 3;
        cp16(smem_u32(&vs[row * AQ_ST + c8]), &vbase[(size_t)row * (KV_ * HD_) + c8]);
    }
    CP_COMMIT();

    float m[2][2] = {{-1e30f, -1e30f}, {-1e30f, -1e30f}};
    float l[2][2] = {};
    float oa[2][16][4] = {};
    uint32_t qs_base = smem_u32(qs);

    const int NT = T_ / 64;
    for (int kt = 0; kt < NT; kt++) {
        int buf = kt & 1;
        if (kt + 1 < NT) {
            int nxt = buf ^ 1;
            int s0g = (kt + 1) * 64;
            #pragma unroll
            for (int p = 0; p < 8; p++) {
                int slot = p * 128 + tid;
                int row = slot >> 4, c8 = (slot & 15) << 3;
                cp16(smem_u32(&ks[nxt * KBUF + row * AQ_ST + c8]),
                     &kbase[(size_t)(s0g + row) * (KV_ * HD_) + c8]);
            }
            #pragma unroll
            for (int p = 0; p < 8; p++) {
                int slot = p * 128 + tid;
                int row = slot >> 4, c8 = (slot & 15) << 3;
                cp16(smem_u32(&vs[nxt * VBUF + row * AQ_ST + c8]),
                     &vbase[(size_t)(s0g + row) * (KV_ * HD_) + c8]);
            }
        }
        CP_COMMIT();
        CP_WAIT1();
        __syncthreads();

        uint32_t ks_base = smem_u32(ks + buf * KBUF);
        uint32_t vs_base = smem_u32(vs + buf * VBUF);

        // S = Q @ K^T : 8 k16 steps over HD=128, 8 n-frags, 2 row-frags.
        float s[2][8][4] = {};
        #pragma unroll
        for (int j = 0; j < 8; j++) {
            int kc = j * 16;
            uint32_t aq[2][4];
            #pragma unroll
            for (int f = 0; f < 2; f++)
                ldsm_x4(aq[f],
                        qs_base + (((r0w + f * 16 + row_off) * AQ_ST) + kc + col_off) * 2);
            uint32_t kb[4][4];
            #pragma unroll
            for (int i = 0; i < 4; i++)
                ldsm_x4(kb[i],
                        ks_base + (((i * 16 + row_off) * AQ_ST) + kc + col_off) * 2);
            #pragma unroll
            for (int nf = 0; nf < 8; nf++) {
                uint32_t b0 = kb[nf >> 1][nf & 1];
                uint32_t b1 = kb[nf >> 1][2 + (nf & 1)];
                #pragma unroll
                for (int f = 0; f < 2; f++)
                    mma_f16(s[f][nf], aq[f][0], aq[f][1], aq[f][2], aq[f][3], b0, b1);
            }
        }

        // Prefetch V fragments for PV step j=0 (trans): overlaps softmax.
        uint32_t vb[8][4];
        #pragma unroll
        for (int i = 0; i < 8; i++)
            ldsm_x4_t(vb[i], vs_base + ((row_off * AQ_ST) + i * 16 + col_off) * 2);

        // Online softmax (exp2 domain); P packed into registers in PV A-layout.
        uint32_t pp[2][8], pq[2][8];
        #pragma unroll
        for (int f = 0; f < 2; f++) {
            float rm1 = -1e30f, rm2 = -1e30f;
            #pragma unroll
            for (int nf = 0; nf < 8; nf++) {
                rm1 = fmaxf(rm1, fmaxf(s[f][nf][0], s[f][nf][1]));
                rm2 = fmaxf(rm2, fmaxf(s[f][nf][2], s[f][nf][3]));
            }
            #pragma unroll
            for (int off = 1; off <= 2; off <<= 1) {
                rm1 = fmaxf(rm1, __shfl_xor_sync(0xffffffffu, rm1, off));
                rm2 = fmaxf(rm2, __shfl_xor_sync(0xffffffffu, rm2, off));
            }
            float m1o = m[f][0], m2o = m[f][1];
            float nm1 = fmaxf(m1o, rm1), nm2 = fmaxf(m2o, rm2);
            float rs1 = 0.f, rs2 = 0.f;
            #pragma unroll
            for (int nf = 0; nf < 8; nf++) {
                float p0 = ex2(s[f][nf][0] - nm1);
                float p1 = ex2(s[f][nf][1] - nm1);
                float p2 = ex2(s[f][nf][2] - nm2);
                float p3 = ex2(s[f][nf][3] - nm2);
                rs1 += p0 + p1; rs2 += p2 + p3;
                pp[f][nf] = pack2(p0, p1);
                pq[f][nf] = pack2(p2, p3);
            }
            #pragma unroll
            for (int off = 1; off <= 2; off <<= 1) {
                rs1 += __shfl_xor_sync(0xffffffffu, rs1, off);
                rs2 += __shfl_xor_sync(0xffffffffu, rs2, off);
            }
            float corr1 = ex2(m1o - nm1), corr2 = ex2(m2o - nm2);
            l[f][0] = l[f][0] * corr1 + rs1; m[f][0] = nm1;
            l[f][1] = l[f][1] * corr2 + rs2; m[f][1] = nm2;
            if (nm1 > m1o || nm2 > m2o) {
                #pragma unroll
                for (int nf = 0; nf < 16; nf++) {
                    oa[f][nf][0] *= corr1; oa[f][nf][1] *= corr1;
                    oa[f][nf][2] *= corr2; oa[f][nf][3] *= corr2;
                }
            }
        }

        // O += P @ V : 4 k16 steps over s=64, 16 n-frags over hd=128.
        #pragma unroll
        for (int j = 0; j < 4; j++) {
            uint32_t vcur[8][4];
            #pragma unroll
            for (int i = 0; i < 8; i++)
                #pragma unroll
                for (int r = 0; r < 4; r++) vcur[i][r] = vb[i][r];
            if (j < 3) {
                int kc = (j + 1) * 16;
                #pragma unroll
                for (int i = 0; i < 8; i++)
                    ldsm_x4_t(vb[i],
                              vs_base + (((kc + row_off) * AQ_ST) + i * 16 + col_off) * 2);
            }
            #pragma unroll
            for (int nf = 0; nf < 16; nf++) {
                uint32_t b0 = vcur[nf >> 1][2 * (nf & 1)];
                uint32_t b1 = vcur[nf >> 1][2 * (nf & 1) + 1];
                #pragma unroll
                for (int f = 0; f < 2; f++)
                    mma_f16(oa[f][nf], pp[f][2 * j], pq[f][2 * j],
                            pp[f][2 * j + 1], pq[f][2 * j + 1], b0, b1);
            }
        }
        __syncthreads();  // compute done before next iter's cp.async overwrites
    }

    #pragma unroll
    for (int f = 0; f < 2; f++) {
        float inv1 = 1.0f / l[f][0], inv2 = 1.0f / l[f][1];
        int rr = r0w + f * 16 + qr;
        size_t base1 = ((size_t)(b * T_ + t0 + rr) * H_ + h) * HD_;
        size_t base2 = ((size_t)(b * T_ + t0 + rr + 8) * H_ + h) * HD_;
        #pragma unroll
        for (int nf = 0; nf < 16; nf++) {
            int c = nf * 8 + ql * 2;
            *(uint32_t*)&oh[base1 + c] = pack2(oa[f][nf][0] * inv1, oa[f][nf][1] * inv1);
            *(uint32_t*)&oh[base2 + c] = pack2(oa[f][nf][2] * inv2, oa[f][nf][3] * inv2);
        }
    }
}

// ---------------------------------------------------------------------------
// Launch
// ---------------------------------------------------------------------------
extern "C" void kernel_launch(void* const* d_in, const int* in_sizes, int n_in,
                              void* d_out, int out_size)
{
    const float* x    = (const float*)d_in[0];
    const float* cosT = (const float*)d_in[1];
    const float* sinT = (const float*)d_in[2];
    const float* Wq   = (const float*)d_in[3];
    const float* Wk   = (const float*)d_in[4];
    const float* Wv   = (const float*)d_in[5];
    const float* Wo   = (const float*)d_in[6];
    const float* qg   = (const float*)d_in[7];
    const float* kg   = (const float*)d_in[8];

    __half *xh, *qr, *kr, *vr, *qh, *kh, *oh, *wt;
    cudaGetSymbolAddress((void**)&xh, g_xh);
    cudaGetSymbolAddress((void**)&qr, g_qr);
    cudaGetSymbolAddress((void**)&kr, g_kr);
    cudaGetSymbolAddress((void**)&vr, g_vr);
    cudaGetSymbolAddress((void**)&qh, g_qh);
    cudaGetSymbolAddress((void**)&kh, g_kh);
    cudaGetSymbolAddress((void**)&oh, g_oh);
    cudaGetSymbolAddress((void**)&wt, g_wt);

    __half* WqkvT = wt;                      // [4096][2048]
    __half* WoT   = wt + 8 * 1024 * 1024;    // [2048][2048]

    const int M = B_ * T_;  // 8192

    transpose_cvt<<<dim3(2048/32, 2048/32), 256>>>(Wq, WqkvT, DM_, 2048);
    transpose_cvt<<<dim3(1024/32, 2048/32), 256>>>(Wk, WqkvT + 2048ull*2048, DM_, 1024);
    transpose_cvt<<<dim3(1024/32, 2048/32), 256>>>(Wv, WqkvT + 3072ull*2048, DM_, 1024);
    transpose_cvt<<<dim3(2048/32, 2048/32), 256>>>(Wo, WoT, H_*HD_, 2048);
    cvt_half<<<(M * DM_) / (256 * 8), 256>>>(x, xh);

    cudaFuncSetAttribute(gemm_f16h, cudaFuncAttributeMaxDynamicSharedMemorySize, GEMM_SMEM);
    gemm_f16h<<<dim3(4096/256, M/128), 256, GEMM_SMEM>>>(xh, WqkvT, nullptr, qr, kr, vr,
                                                         M, 4096, DM_);

    const float qscale = 0.0883883476483184405f * 1.4426950408889634f;
    rmsrope_h<<<(M * H_) / 8, 256>>>(qr, qh, qg, cosT, sinT, H_, qscale);
    rmsrope_h<<<(M * KV_) / 8, 256>>>(kr, kh, kg, cosT, sinT, KV_, 1.0f);

    cudaFuncSetAttribute(attn_f16, cudaFuncAttributeMaxDynamicSharedMemorySize, ATTN_SMEM);
    attn_f16<<<dim3(T_ / 128, H_, B_), 128, ATTN_SMEM>>>(qh, kh, vr, oh);

    gemm_f16h<<<dim3(DM_/256, M/128), 256, GEMM_SMEM>>>(oh, WoT, (float*)d_out,
                                                        nullptr, nullptr, nullptr,
                                                        M, DM_, DM_);
}

// round 15
// speedup vs baseline: 1.0141x; 1.0057x over previous
#include <cuda_runtime.h>
#include <cuda_fp16.h>
#include <math.h>
#include <stdint.h>

#define B_ 4
#define T_ 2048
#define DM_ 2048
#define H_ 16
#define KV_ 8
#define HD_ 128
#define G_ 2

// Scratch (no allocations allowed) — static device globals.
__device__ __half g_xh[B_*T_*DM_];
__device__ __half g_qh[B_*T_*H_*HD_];
__device__ __half g_kh[B_*T_*KV_*HD_];
__device__ __half g_vr[B_*T_*KV_*HD_];
__device__ __half g_oh[B_*T_*H_*HD_];
__device__ __half g_wt[12*1024*1024];   // WqkvT [4096][2048], WoT [2048][2048]

// ---------------------------------------------------------------------------
// Helpers
// ---------------------------------------------------------------------------
__device__ __forceinline__ uint32_t h2u(__half2 h) { return *(uint32_t*)&h; }
__device__ __forceinline__ uint32_t pack2(float lo, float hi) {
    return h2u(__floats2half2_rn(lo, hi));
}
__device__ __forceinline__ float ex2(float x) {
    float r;
    asm("ex2.approx.f32 %0, %1;" : "=f"(r) : "f"(x));
    return r;
}

__device__ __forceinline__ void mma_f16(float c[4],
                                        uint32_t a0, uint32_t a1, uint32_t a2, uint32_t a3,
                                        uint32_t b0, uint32_t b1) {
    asm volatile(
        "mma.sync.aligned.m16n8k16.row.col.f32.f16.f16.f32 "
        "{%0,%1,%2,%3}, {%4,%5,%6,%7}, {%8,%9}, {%0,%1,%2,%3};"
        : "+f"(c[0]), "+f"(c[1]), "+f"(c[2]), "+f"(c[3])
        : "r"(a0), "r"(a1), "r"(a2), "r"(a3), "r"(b0), "r"(b1));
}

// ldmatrix x4 (non-trans): A-frags / B-frags from [row][k] tiles.
__device__ __forceinline__ void ldsm_x4(uint32_t* d, uint32_t addr) {
    asm volatile("ldmatrix.sync.aligned.m8n8.x4.shared.b16 {%0,%1,%2,%3}, [%4];"
                 : "=r"(d[0]), "=r"(d[1]), "=r"(d[2]), "=r"(d[3]) : "r"(addr));
}
// ldmatrix x4 trans: B-frags (Vᵀ) from row-major [k(s)][n(hd)] tiles.
__device__ __forceinline__ void ldsm_x4_t(uint32_t* d, uint32_t addr) {
    asm volatile("ldmatrix.sync.aligned.m8n8.x4.trans.shared.b16 {%0,%1,%2,%3}, [%4];"
                 : "=r"(d[0]), "=r"(d[1]), "=r"(d[2]), "=r"(d[3]) : "r"(addr));
}

__device__ __forceinline__ uint32_t smem_u32(const void* p) {
    uint32_t a;
    asm("{ .reg .u64 t; cvta.to.shared.u64 t, %1; cvt.u32.u64 %0, t; }" : "=r"(a) : "l"(p));
    return a;
}
__device__ __forceinline__ void cp16(uint32_t s, const void* g) {
    asm volatile("cp.async.ca.shared.global [%0], [%1], 16;" :: "r"(s), "l"(g));
}
#define CP_COMMIT() asm volatile("cp.async.commit_group;")
#define CP_WAIT1()  asm volatile("cp.async.wait_group 1;")

// ---------------------------------------------------------------------------
// All four weight transposes (fp32 -> fp16, W[K][N] -> WT[N][K]) in ONE launch.
// blockIdx.z: 0=Wq(N2048) 1=Wk(N1024) 2=Wv(N1024) 3=Wo(N2048). K=2048 for all.
// ---------------------------------------------------------------------------
__global__ void transpose_all(const float* __restrict__ Wq, const float* __restrict__ Wk,
                              const float* __restrict__ Wv, const float* __restrict__ Wo,
                              __half* __restrict__ WT)
{
    __shared__ float t[32][33];
    int z = blockIdx.z;
    const float* W; __half* dst; int N;
    if (z == 0)      { W = Wq; N = 2048; dst = WT; }
    else if (z == 1) { W = Wk; N = 1024; dst = WT + 2048ull * 2048; }
    else if (z == 2) { W = Wv; N = 1024; dst = WT + 3072ull * 2048; }
    else             { W = Wo; N = 2048; dst = WT + 8ull * 1024 * 1024; }
    int n0 = blockIdx.x * 32, k0 = blockIdx.y * 32;
    if (n0 >= N) return;
    const int K = 2048;
    int tx = threadIdx.x & 31, ty = threadIdx.x >> 5;
    #pragma unroll
    for (int j = 0; j < 4; j++)
        t[ty + 8 * j][tx] = W[(size_t)(k0 + ty + 8 * j) * N + n0 + tx];
    __syncthreads();
    #pragma unroll
    for (int j = 0; j < 4; j++)
        dst[(size_t)(n0 + ty + 8 * j) * K + k0 + tx] = __float2half_rn(t[tx][ty + 8 * j]);
}

// fp32 -> fp16 bulk convert (8 elements/thread).
__global__ void cvt_half(const float* __restrict__ in, __half* __restrict__ out)
{
    size_t i = ((size_t)blockIdx.x * blockDim.x + threadIdx.x) * 8;
    float4 a = *(const float4*)&in[i];
    float4 b = *(const float4*)&in[i + 4];
    *(uint4*)&out[i] = make_uint4(pack2(a.x, a.y), pack2(a.z, a.w),
                                  pack2(b.x, b.y), pack2(b.z, b.w));
}

// ---------------------------------------------------------------------------
// All-fp16 pipelined GEMM: block 128x256, BK=64, cp.async 2-stage,
// 256 threads = 8 warps (2m x 4n of 64x64 tiles), m16n8k16, ldmatrix frags.
// Two epilogues:
//   Cf != null : plain fp32 store (Wo GEMM).
//   else       : fused QKV — RMSNorm (+gamma) + interleaved RoPE applied to
//                q (cols [0,2048), scale qscale) and k (cols [2048,3072)),
//                plain fp16 store for v (cols [3072,4096)).
// RMSNorm row sums: quad shfl within a warp (64 cols) + smem exchange with
// the partner warp (wg^1) holding the other 64 cols of the head.
// ---------------------------------------------------------------------------
#define GST 72
#define GT_A (128 * GST)
#define GT_B (256 * GST)
#define GEMM_SMEM ((2 * (GT_A + GT_B)) * 2)   // 110592 bytes

__global__ __launch_bounds__(256, 1)
void gemm_f16h(const __half* __restrict__ A, const __half* __restrict__ WT,
               float* __restrict__ Cf,
               __half* __restrict__ Hq, __half* __restrict__ Hk, __half* __restrict__ Hv,
               const float* __restrict__ qg, const float* __restrict__ kg,
               const float* __restrict__ cosT, const float* __restrict__ sinT,
               float qscale, int M, int N, int K)
{
    extern __shared__ __half gsm[];
    __half* As[2] = { gsm, gsm + GT_A };
    __half* Bs[2] = { gsm + 2 * GT_A, gsm + 2 * GT_A + GT_B };

    int tid  = threadIdx.x;
    int lane = tid & 31;
    int warp = tid >> 5;
    int qr = lane >> 2, ql = lane & 3;
    int row_off = lane & 15;
    int col_off = (lane >> 4) << 3;
    int wm = (warp & 1) * 64;
    int wn = (warp >> 1) * 64;
    int bm = blockIdx.y * 128, bn = blockIdx.x * 256;

    float acc[4][8][4] = {};   // warp tile 64x64
    const int NT = K / 64;

    #pragma unroll
    for (int p = 0; p < 4; p++) {
        int slot = p * 256 + tid;
        int r = slot >> 3, c8 = (slot & 7) << 3;
        cp16(smem_u32(&As[0][r * GST + c8]), &A[(size_t)(bm + r) * K + c8]);
    }
    #pragma unroll
    for (int p = 0; p < 8; p++) {
        int slot = p * 256 + tid;
        int r = slot >> 3, c8 = (slot & 7) << 3;
        cp16(smem_u32(&Bs[0][r * GST + c8]), &WT[(size_t)(bn + r) * K + c8]);
    }
    CP_COMMIT();

    for (int kt = 0; kt < NT; kt++) {
        int buf = kt & 1;
        if (kt + 1 < NT) {
            int nxt = buf ^ 1;
            int k0 = (kt + 1) * 64;
            #pragma unroll
            for (int p = 0; p < 4; p++) {
                int slot = p * 256 + tid;
                int r = slot >> 3, c8 = (slot & 7) << 3;
                cp16(smem_u32(&As[nxt][r * GST + c8]), &A[(size_t)(bm + r) * K + k0 + c8]);
            }
            #pragma unroll
            for (int p = 0; p < 8; p++) {
                int slot = p * 256 + tid;
                int r = slot >> 3, c8 = (slot & 7) << 3;
                cp16(smem_u32(&Bs[nxt][r * GST + c8]), &WT[(size_t)(bn + r) * K + k0 + c8]);
            }
        }
        CP_COMMIT();
        CP_WAIT1();
        __syncthreads();

        uint32_t a_base = smem_u32(As[buf]);
        uint32_t b_base = smem_u32(Bs[buf]);
        #pragma unroll
        for (int ks = 0; ks < 4; ks++) {
            int kc = ks * 16;
            uint32_t af[4][4];
            #pragma unroll
            for (int fm = 0; fm < 4; fm++)
                ldsm_x4(af[fm],
                        a_base + (((wm + fm * 16 + row_off) * GST) + kc + col_off) * 2);
            uint32_t bf[4][4];
            #pragma unroll
            for (int i = 0; i < 4; i++)
                ldsm_x4(bf[i],
                        b_base + (((wn + i * 16 + row_off) * GST) + kc + col_off) * 2);
            #pragma unroll
            for (int fn = 0; fn < 8; fn++) {
                uint32_t b0 = bf[fn >> 1][fn & 1];
                uint32_t b1 = bf[fn >> 1][2 + (fn & 1)];
                #pragma unroll
                for (int fm = 0; fm < 4; fm++)
                    mma_f16(acc[fm][fn], af[fm][0], af[fm][1], af[fm][2], af[fm][3], b0, b1);
            }
        }
        __syncthreads();
    }

    if (Cf) {
        // Plain fp32 epilogue (Wo GEMM).
        #pragma unroll
        for (int fm = 0; fm < 4; fm++) {
            #pragma unroll
            for (int fn = 0; fn < 8; fn++) {
                int r = bm + wm + fm * 16 + qr;
                int c = bn + wn + fn * 8 + ql * 2;
                *(float2*)&Cf[(size_t)r * N + c]       = make_float2(acc[fm][fn][0], acc[fm][fn][1]);
                *(float2*)&Cf[(size_t)(r + 8) * N + c] = make_float2(acc[fm][fn][2], acc[fm][fn][3]);
            }
        }
        return;
    }

    // Fused QKV epilogue.
    bool isV = (bn >= 3072);
    float* rs = (float*)gsm;   // [4][128] row sum-of-squares partials (2 KB)
    int wg = warp >> 1;

    if (!isV) {
        #pragma unroll
        for (int fm = 0; fm < 4; fm++) {
            float p1 = 0.f, p2 = 0.f;
            #pragma unroll
            for (int fn = 0; fn < 8; fn++) {
                p1 += acc[fm][fn][0] * acc[fm][fn][0] + acc[fm][fn][1] * acc[fm][fn][1];
                p2 += acc[fm][fn][2] * acc[fm][fn][2] + acc[fm][fn][3] * acc[fm][fn][3];
            }
            p1 += __shfl_xor_sync(0xffffffffu, p1, 1);
            p1 += __shfl_xor_sync(0xffffffffu, p1, 2);
            p2 += __shfl_xor_sync(0xffffffffu, p2, 1);
            p2 += __shfl_xor_sync(0xffffffffu, p2, 2);
            if (ql == 0) {
                rs[wg * 128 + wm + fm * 16 + qr]     = p1;
                rs[wg * 128 + wm + fm * 16 + qr + 8] = p2;
            }
        }
        __syncthreads();
    }

    __half* Hb; int ldc, cofs; const float* gam; float sc;
    if (bn < 2048)      { Hb = Hq; ldc = 2048; cofs = bn;        gam = qg; sc = qscale; }
    else if (bn < 3072) { Hb = Hk; ldc = 1024; cofs = bn - 2048; gam = kg; sc = 1.0f; }
    else                { Hb = Hv; ldc = 1024; cofs = bn - 3072; gam = nullptr; sc = 0.f; }

    #pragma unroll
    for (int fm = 0; fm < 4; fm++) {
        int rb1 = wm + fm * 16 + qr;
        int rb2 = rb1 + 8;
        int rg1 = bm + rb1, rg2 = bm + rb2;
        if (isV) {
            #pragma unroll
            for (int fn = 0; fn < 8; fn++) {
                int c = cofs + wn + fn * 8 + ql * 2;
                *(uint32_t*)&Hb[(size_t)rg1 * ldc + c] = pack2(acc[fm][fn][0], acc[fm][fn][1]);
                *(uint32_t*)&Hb[(size_t)rg2 * ldc + c] = pack2(acc[fm][fn][2], acc[fm][fn][3]);
            }
        } else {
            float tot1 = rs[wg * 128 + rb1] + rs[(wg ^ 1) * 128 + rb1];
            float tot2 = rs[wg * 128 + rb2] + rs[(wg ^ 1) * 128 + rb2];
            float inv1 = rsqrtf(tot1 * (1.0f / HD_) + 1e-6f);
            float inv2 = rsqrtf(tot2 * (1.0f / HD_) + 1e-6f);
            int t1 = rg1 & (T_ - 1), t2 = rg2 & (T_ - 1);
            #pragma unroll
            for (int fn = 0; fn < 8; fn++) {
                int c  = cofs + wn + fn * 8 + ql * 2;
                int cc = c & 127;
                float g0 = gam[cc], g1 = gam[cc + 1];
                float c1 = cosT[t1 * HD_ + cc], s1 = sinT[t1 * HD_ + cc];
                float c2 = cosT[t2 * HD_ + cc], s2 = sinT[t2 * HD_ + cc];
                float h0 = acc[fm][fn][0] * inv1 * g0;
                float h1 = acc[fm][fn][1] * inv1 * g1;
                *(uint32_t*)&Hb[(size_t)rg1 * ldc + c] =
                    pack2((h0 * c1 - h1 * s1) * sc, (h1 * c1 + h0 * s1) * sc);
                h0 = acc[fm][fn][2] * inv2 * g0;
                h1 = acc[fm][fn][3] * inv2 * g1;
                *(uint32_t*)&Hb[(size_t)rg2 * ldc + c] =
                    pack2((h0 * c2 - h1 * s2) * sc, (h1 * c2 + h0 * s2) * sc);
            }
        }
    }
}

// ---------------------------------------------------------------------------
// FP16 flash attention: 128 q-rows/CTA, 128 threads = 4 warps (32 rows each),
// 2 CTAs/SM. 64-wide K/V tiles cp.async double-buffered, m16n8k16 QK^T/PV.
// V row-major, transposed on load via ldmatrix.trans; V j=0 frags prefetched
// ahead of the softmax; P stays in registers. (R13 state — unchanged.)
// ---------------------------------------------------------------------------
#define AQ_ST 136
#define KBUF (64 * AQ_ST)
#define VBUF (64 * AQ_ST)
#define ATTN_SMEM ((128*AQ_ST + 2*KBUF + 2*VBUF) * 2)   // 104448 B -> 2 CTA/SM

__global__ __launch_bounds__(128, 2)
void attn_f16(const __half* __restrict__ qh, const __half* __restrict__ kh,
              const __half* __restrict__ vr, __half* __restrict__ oh)
{
    extern __shared__ __half hsm[];
    __half* qs = hsm;                       // 128 x 136
    __half* ks = qs + 128 * AQ_ST;          // 2 x (64 x 136)
    __half* vs = ks + 2 * KBUF;             // 2 x (64 x 136), row-major [s][hd]

    int b = blockIdx.z, h = blockIdx.y;
    int kvh = h / G_;
    int t0 = blockIdx.x * 128;
    int tid = threadIdx.x, lane = tid & 31, warp = tid >> 5;
    int qr = lane >> 2;
    int ql = lane & 3;
    int row_off = lane & 15;
    int col_off = (lane >> 4) << 3;
    int r0w = warp * 32;

    const __half* kbase = kh + ((size_t)(b * T_) * KV_ + kvh) * HD_;
    const __half* vbase = vr + ((size_t)(b * T_) * KV_ + kvh) * HD_;

    #pragma unroll
    for (int p = 0; p < 16; p++) {
        int slot = p * 128 + tid;
        int row = slot >> 4, c8 = (slot & 15) << 3;
        cp16(smem_u32(&qs[row * AQ_ST + c8]),
             &qh[((size_t)(b * T_ + t0 + row) * H_ + h) * HD_ + c8]);
    }
    #pragma unroll
    for (int p = 0; p < 8; p++) {
        int slot = p * 128 + tid;
        int row = slot >> 4, c8 = (slot & 15) << 3;
        cp16(smem_u32(&ks[row * AQ_ST + c8]), &kbase[(size_t)row * (KV_ * HD_) + c8]);
    }
    #pragma unroll
    for (int p = 0; p < 8; p++) {
        int slot = p * 128 + tid;
        int row = slot >> 4, c8 = (slot & 15) << 3;
        cp16(smem_u32(&vs[row * AQ_ST + c8]), &vbase[(size_t)row * (KV_ * HD_) + c8]);
    }
    CP_COMMIT();

    float m[2][2] = {{-1e30f, -1e30f}, {-1e30f, -1e30f}};
    float l[2][2] = {};
    float oa[2][16][4] = {};
    uint32_t qs_base = smem_u32(qs);

    const int NT = T_ / 64;
    for (int kt = 0; kt < NT; kt++) {
        int buf = kt & 1;
        if (kt + 1 < NT) {
            int nxt = buf ^ 1;
            int s0g = (kt + 1) * 64;
            #pragma unroll
            for (int p = 0; p < 8; p++) {
                int slot = p * 128 + tid;
                int row = slot >> 4, c8 = (slot & 15) << 3;
                cp16(smem_u32(&ks[nxt * KBUF + row * AQ_ST + c8]),
                     &kbase[(size_t)(s0g + row) * (KV_ * HD_) + c8]);
            }
            #pragma unroll
            for (int p = 0; p < 8; p++) {
                int slot = p * 128 + tid;
                int row = slot >> 4, c8 = (slot & 15) << 3;
                cp16(smem_u32(&vs[nxt * VBUF + row * AQ_ST + c8]),
                     &vbase[(size_t)(s0g + row) * (KV_ * HD_) + c8]);
            }
        }
        CP_COMMIT();
        CP_WAIT1();
        __syncthreads();

        uint32_t ks_base = smem_u32(ks + buf * KBUF);
        uint32_t vs_base = smem_u32(vs + buf * VBUF);

        float s[2][8][4] = {};
        #pragma unroll
        for (int j = 0; j < 8; j++) {
            int kc = j * 16;
            uint32_t aq[2][4];
            #pragma unroll
            for (int f = 0; f < 2; f++)
                ldsm_x4(aq[f],
                        qs_base + (((r0w + f * 16 + row_off) * AQ_ST) + kc + col_off) * 2);
            uint32_t kb[4][4];
            #pragma unroll
            for (int i = 0; i < 4; i++)
                ldsm_x4(kb[i],
                        ks_base + (((i * 16 + row_off) * AQ_ST) + kc + col_off) * 2);
            #pragma unroll
            for (int nf = 0; nf < 8; nf++) {
                uint32_t b0 = kb[nf >> 1][nf & 1];
                uint32_t b1 = kb[nf >> 1][2 + (nf & 1)];
                #pragma unroll
                for (int f = 0; f < 2; f++)
                    mma_f16(s[f][nf], aq[f][0], aq[f][1], aq[f][2], aq[f][3], b0, b1);
            }
        }

        uint32_t vb[8][4];
        #pragma unroll
        for (int i = 0; i < 8; i++)
            ldsm_x4_t(vb[i], vs_base + ((row_off * AQ_ST) + i * 16 + col_off) * 2);

        uint32_t pp[2][8], pq[2][8];
        #pragma unroll
        for (int f = 0; f < 2; f++) {
            float rm1 = -1e30f, rm2 = -1e30f;
            #pragma unroll
            for (int nf = 0; nf < 8; nf++) {
                rm1 = fmaxf(rm1, fmaxf(s[f][nf][0], s[f][nf][1]));
                rm2 = fmaxf(rm2, fmaxf(s[f][nf][2], s[f][nf][3]));
            }
            #pragma unroll
            for (int off = 1; off <= 2; off <<= 1) {
                rm1 = fmaxf(rm1, __shfl_xor_sync(0xffffffffu, rm1, off));
                rm2 = fmaxf(rm2, __shfl_xor_sync(0xffffffffu, rm2, off));
            }
            float m1o = m[f][0], m2o = m[f][1];
            float nm1 = fmaxf(m1o, rm1), nm2 = fmaxf(m2o, rm2);
            float rs1 = 0.f, rs2 = 0.f;
            #pragma unroll
            for (int nf = 0; nf < 8; nf++) {
                float p0 = ex2(s[f][nf][0] - nm1);
                float p1 = ex2(s[f][nf][1] - nm1);
                float p2 = ex2(s[f][nf][2] - nm2);
                float p3 = ex2(s[f][nf][3] - nm2);
                rs1 += p0 + p1; rs2 += p2 + p3;
                pp[f][nf] = pack2(p0, p1);
                pq[f][nf] = pack2(p2, p3);
            }
            #pragma unroll
            for (int off = 1; off <= 2; off <<= 1) {
                rs1 += __shfl_xor_sync(0xffffffffu, rs1, off);
                rs2 += __shfl_xor_sync(0xffffffffu, rs2, off);
            }
            float corr1 = ex2(m1o - nm1), corr2 = ex2(m2o - nm2);
            l[f][0] = l[f][0] * corr1 + rs1; m[f][0] = nm1;
            l[f][1] = l[f][1] * corr2 + rs2; m[f][1] = nm2;
            if (nm1 > m1o || nm2 > m2o) {
                #pragma unroll
                for (int nf = 0; nf < 16; nf++) {
                    oa[f][nf][0] *= corr1; oa[f][nf][1] *= corr1;
                    oa[f][nf][2] *= corr2; oa[f][nf][3] *= corr2;
                }
            }
        }

        #pragma unroll
        for (int j = 0; j < 4; j++) {
            uint32_t vcur[8][4];
            #pragma unroll
            for (int i = 0; i < 8; i++)
                #pragma unroll
                for (int r = 0; r < 4; r++) vcur[i][r] = vb[i][r];
            if (j < 3) {
                int kc = (j + 1) * 16;
                #pragma unroll
                for (int i = 0; i < 8; i++)
                    ldsm_x4_t(vb[i],
                              vs_base + (((kc + row_off) * AQ_ST) + i * 16 + col_off) * 2);
            }
            #pragma unroll
            for (int nf = 0; nf < 16; nf++) {
                uint32_t b0 = vcur[nf >> 1][2 * (nf & 1)];
                uint32_t b1 = vcur[nf >> 1][2 * (nf & 1) + 1];
                #pragma unroll
                for (int f = 0; f < 2; f++)
                    mma_f16(oa[f][nf], pp[f][2 * j], pq[f][2 * j],
                            pp[f][2 * j + 1], pq[f][2 * j + 1], b0, b1);
            }
        }
        __syncthreads();
    }

    #pragma unroll
    for (int f = 0; f < 2; f++) {
        float inv1 = 1.0f / l[f][0], inv2 = 1.0f / l[f][1];
        int rr = r0w + f * 16 + qr;
        size_t base1 = ((size_t)(b * T_ + t0 + rr) * H_ + h) * HD_;
        size_t base2 = ((size_t)(b * T_ + t0 + rr + 8) * H_ + h) * HD_;
        #pragma unroll
        for (int nf = 0; nf < 16; nf++) {
            int c = nf * 8 + ql * 2;
            *(uint32_t*)&oh[base1 + c] = pack2(oa[f][nf][0] * inv1, oa[f][nf][1] * inv1);
            *(uint32_t*)&oh[base2 + c] = pack2(oa[f][nf][2] * inv2, oa[f][nf][3] * inv2);
        }
    }
}

// ---------------------------------------------------------------------------
// Launch
// ---------------------------------------------------------------------------
extern "C" void kernel_launch(void* const* d_in, const int* in_sizes, int n_in,
                              void* d_out, int out_size)
{
    const float* x    = (const float*)d_in[0];
    const float* cosT = (const float*)d_in[1];
    const float* sinT = (const float*)d_in[2];
    const float* Wq   = (const float*)d_in[3];
    const float* Wk   = (const float*)d_in[4];
    const float* Wv   = (const float*)d_in[5];
    const float* Wo   = (const float*)d_in[6];
    const float* qg   = (const float*)d_in[7];
    const float* kg   = (const float*)d_in[8];

    __half *xh, *qh, *kh, *vr, *oh, *wt;
    cudaGetSymbolAddress((void**)&xh, g_xh);
    cudaGetSymbolAddress((void**)&qh, g_qh);
    cudaGetSymbolAddress((void**)&kh, g_kh);
    cudaGetSymbolAddress((void**)&vr, g_vr);
    cudaGetSymbolAddress((void**)&oh, g_oh);
    cudaGetSymbolAddress((void**)&wt, g_wt);

    __half* WqkvT = wt;                      // [4096][2048]
    __half* WoT   = wt + 8 * 1024 * 1024;    // [2048][2048]

    const int M = B_ * T_;  // 8192

    transpose_all<<<dim3(64, 64, 4), 256>>>(Wq, Wk, Wv, Wo, wt);
    cvt_half<<<(M * DM_) / (256 * 8), 256>>>(x, xh);

    // q gets 1/sqrt(HD) * log2(e) for the exp2-domain softmax (fused epilogue).
    const float qscale = 0.0883883476483184405f * 1.4426950408889634f;

    cudaFuncSetAttribute(gemm_f16h, cudaFuncAttributeMaxDynamicSharedMemorySize, GEMM_SMEM);
    gemm_f16h<<<dim3(4096/256, M/128), 256, GEMM_SMEM>>>(
        xh, WqkvT, nullptr, qh, kh, vr, qg, kg, cosT, sinT, qscale, M, 4096, DM_);

    cudaFuncSetAttribute(attn_f16, cudaFuncAttributeMaxDynamicSharedMemorySize, ATTN_SMEM);
    attn_f16<<<dim3(T_ / 128, H_, B_), 128, ATTN_SMEM>>>(qh, kh, vr, oh);

    gemm_f16h<<<dim3(DM_/256, M/128), 256, GEMM_SMEM>>>(
        oh, WoT, (float*)d_out, nullptr, nullptr, nullptr,
        nullptr, nullptr, nullptr, nullptr, 0.f, M, DM_, DM_);
}

// round 16
// speedup vs baseline: 1.0183x; 1.0040x over previous
#include <cuda_runtime.h>
#include <cuda_fp16.h>
#include <math.h>
#include <stdint.h>

#define B_ 4
#define T_ 2048
#define DM_ 2048
#define H_ 16
#define KV_ 8
#define HD_ 128
#define G_ 2

// Scratch (no allocations allowed) — static device globals.
__device__ __half g_xh[B_*T_*DM_];
__device__ __half g_qh[B_*T_*H_*HD_];
__device__ __half g_kh[B_*T_*KV_*HD_];
__device__ __half g_vr[B_*T_*KV_*HD_];
__device__ __half g_oh[B_*T_*H_*HD_];
__device__ __half g_wt[12*1024*1024];   // WqkvT [4096][2048], WoT [2048][2048]

// ---------------------------------------------------------------------------
// Helpers
// ---------------------------------------------------------------------------
__device__ __forceinline__ uint32_t h2u(__half2 h) { return *(uint32_t*)&h; }
__device__ __forceinline__ uint32_t pack2(float lo, float hi) {
    return h2u(__floats2half2_rn(lo, hi));
}
__device__ __forceinline__ float ex2(float x) {
    float r;
    asm("ex2.approx.f32 %0, %1;" : "=f"(r) : "f"(x));
    return r;
}

__device__ __forceinline__ void mma_f16(float c[4],
                                        uint32_t a0, uint32_t a1, uint32_t a2, uint32_t a3,
                                        uint32_t b0, uint32_t b1) {
    asm volatile(
        "mma.sync.aligned.m16n8k16.row.col.f32.f16.f16.f32 "
        "{%0,%1,%2,%3}, {%4,%5,%6,%7}, {%8,%9}, {%0,%1,%2,%3};"
        : "+f"(c[0]), "+f"(c[1]), "+f"(c[2]), "+f"(c[3])
        : "r"(a0), "r"(a1), "r"(a2), "r"(a3), "r"(b0), "r"(b1));
}

// ldmatrix x4 (non-trans): A-frags / B-frags from [row][k] tiles.
__device__ __forceinline__ void ldsm_x4(uint32_t* d, uint32_t addr) {
    asm volatile("ldmatrix.sync.aligned.m8n8.x4.shared.b16 {%0,%1,%2,%3}, [%4];"
                 : "=r"(d[0]), "=r"(d[1]), "=r"(d[2]), "=r"(d[3]) : "r"(addr));
}
// ldmatrix x4 trans: B-frags (Vᵀ) from row-major [k(s)][n(hd)] tiles.
__device__ __forceinline__ void ldsm_x4_t(uint32_t* d, uint32_t addr) {
    asm volatile("ldmatrix.sync.aligned.m8n8.x4.trans.shared.b16 {%0,%1,%2,%3}, [%4];"
                 : "=r"(d[0]), "=r"(d[1]), "=r"(d[2]), "=r"(d[3]) : "r"(addr));
}

__device__ __forceinline__ uint32_t smem_u32(const void* p) {
    uint32_t a;
    asm("{ .reg .u64 t; cvta.to.shared.u64 t, %1; cvt.u32.u64 %0, t; }" : "=r"(a) : "l"(p));
    return a;
}
__device__ __forceinline__ void cp16(uint32_t s, const void* g) {
    asm volatile("cp.async.ca.shared.global [%0], [%1], 16;" :: "r"(s), "l"(g));
}
#define CP_COMMIT() asm volatile("cp.async.commit_group;")
#define CP_WAIT1()  asm volatile("cp.async.wait_group 1;")

// ---------------------------------------------------------------------------
// All four weight transposes (fp32 -> fp16, W[K][N] -> WT[N][K]) in ONE launch.
// ---------------------------------------------------------------------------
__global__ void transpose_all(const float* __restrict__ Wq, const float* __restrict__ Wk,
                              const float* __restrict__ Wv, const float* __restrict__ Wo,
                              __half* __restrict__ WT)
{
    __shared__ float t[32][33];
    int z = blockIdx.z;
    const float* W; __half* dst; int N;
    if (z == 0)      { W = Wq; N = 2048; dst = WT; }
    else if (z == 1) { W = Wk; N = 1024; dst = WT + 2048ull * 2048; }
    else if (z == 2) { W = Wv; N = 1024; dst = WT + 3072ull * 2048; }
    else             { W = Wo; N = 2048; dst = WT + 8ull * 1024 * 1024; }
    int n0 = blockIdx.x * 32, k0 = blockIdx.y * 32;
    if (n0 >= N) return;
    const int K = 2048;
    int tx = threadIdx.x & 31, ty = threadIdx.x >> 5;
    #pragma unroll
    for (int j = 0; j < 4; j++)
        t[ty + 8 * j][tx] = W[(size_t)(k0 + ty + 8 * j) * N + n0 + tx];
    __syncthreads();
    #pragma unroll
    for (int j = 0; j < 4; j++)
        dst[(size_t)(n0 + ty + 8 * j) * K + k0 + tx] = __float2half_rn(t[tx][ty + 8 * j]);
}

// fp32 -> fp16 bulk convert (8 elements/thread).
__global__ void cvt_half(const float* __restrict__ in, __half* __restrict__ out)
{
    size_t i = ((size_t)blockIdx.x * blockDim.x + threadIdx.x) * 8;
    float4 a = *(const float4*)&in[i];
    float4 b = *(const float4*)&in[i + 4];
    *(uint4*)&out[i] = make_uint4(pack2(a.x, a.y), pack2(a.z, a.w),
                                  pack2(b.x, b.y), pack2(b.z, b.w));
}

// ---------------------------------------------------------------------------
// All-fp16 pipelined GEMM: block 128x256, BK=64, cp.async 2-stage,
// 256 threads = 8 warps (2m x 4n of 64x64 tiles), m16n8k16, ldmatrix frags.
//   Cf != null : plain fp32 store (Wo GEMM).
//   else       : fused QKV — RMSNorm+RoPE on q/k, plain fp16 store for v.
// ---------------------------------------------------------------------------
#define GST 72
#define GT_A (128 * GST)
#define GT_B (256 * GST)
#define GEMM_SMEM ((2 * (GT_A + GT_B)) * 2)   // 110592 bytes

__global__ __launch_bounds__(256, 1)
void gemm_f16h(const __half* __restrict__ A, const __half* __restrict__ WT,
               float* __restrict__ Cf,
               __half* __restrict__ Hq, __half* __restrict__ Hk, __half* __restrict__ Hv,
               const float* __restrict__ qg, const float* __restrict__ kg,
               const float* __restrict__ cosT, const float* __restrict__ sinT,
               float qscale, int M, int N, int K)
{
    extern __shared__ __half gsm[];
    __half* As[2] = { gsm, gsm + GT_A };
    __half* Bs[2] = { gsm + 2 * GT_A, gsm + 2 * GT_A + GT_B };

    int tid  = threadIdx.x;
    int lane = tid & 31;
    int warp = tid >> 5;
    int qr = lane >> 2, ql = lane & 3;
    int row_off = lane & 15;
    int col_off = (lane >> 4) << 3;
    int wm = (warp & 1) * 64;
    int wn = (warp >> 1) * 64;
    int bm = blockIdx.y * 128, bn = blockIdx.x * 256;

    float acc[4][8][4] = {};
    const int NT = K / 64;

    #pragma unroll
    for (int p = 0; p < 4; p++) {
        int slot = p * 256 + tid;
        int r = slot >> 3, c8 = (slot & 7) << 3;
        cp16(smem_u32(&As[0][r * GST + c8]), &A[(size_t)(bm + r) * K + c8]);
    }
    #pragma unroll
    for (int p = 0; p < 8; p++) {
        int slot = p * 256 + tid;
        int r = slot >> 3, c8 = (slot & 7) << 3;
        cp16(smem_u32(&Bs[0][r * GST + c8]), &WT[(size_t)(bn + r) * K + c8]);
    }
    CP_COMMIT();

    for (int kt = 0; kt < NT; kt++) {
        int buf = kt & 1;
        if (kt + 1 < NT) {
            int nxt = buf ^ 1;
            int k0 = (kt + 1) * 64;
            #pragma unroll
            for (int p = 0; p < 4; p++) {
                int slot = p * 256 + tid;
                int r = slot >> 3, c8 = (slot & 7) << 3;
                cp16(smem_u32(&As[nxt][r * GST + c8]), &A[(size_t)(bm + r) * K + k0 + c8]);
            }
            #pragma unroll
            for (int p = 0; p < 8; p++) {
                int slot = p * 256 + tid;
                int r = slot >> 3, c8 = (slot & 7) << 3;
                cp16(smem_u32(&Bs[nxt][r * GST + c8]), &WT[(size_t)(bn + r) * K + k0 + c8]);
            }
        }
        CP_COMMIT();
        CP_WAIT1();
        __syncthreads();

        uint32_t a_base = smem_u32(As[buf]);
        uint32_t b_base = smem_u32(Bs[buf]);
        #pragma unroll
        for (int ks = 0; ks < 4; ks++) {
            int kc = ks * 16;
            uint32_t af[4][4];
            #pragma unroll
            for (int fm = 0; fm < 4; fm++)
                ldsm_x4(af[fm],
                        a_base + (((wm + fm * 16 + row_off) * GST) + kc + col_off) * 2);
            uint32_t bf[4][4];
            #pragma unroll
            for (int i = 0; i < 4; i++)
                ldsm_x4(bf[i],
                        b_base + (((wn + i * 16 + row_off) * GST) + kc + col_off) * 2);
            #pragma unroll
            for (int fn = 0; fn < 8; fn++) {
                uint32_t b0 = bf[fn >> 1][fn & 1];
                uint32_t b1 = bf[fn >> 1][2 + (fn & 1)];
                #pragma unroll
                for (int fm = 0; fm < 4; fm++)
                    mma_f16(acc[fm][fn], af[fm][0], af[fm][1], af[fm][2], af[fm][3], b0, b1);
            }
        }
        __syncthreads();
    }

    if (Cf) {
        #pragma unroll
        for (int fm = 0; fm < 4; fm++) {
            #pragma unroll
            for (int fn = 0; fn < 8; fn++) {
                int r = bm + wm + fm * 16 + qr;
                int c = bn + wn + fn * 8 + ql * 2;
                *(float2*)&Cf[(size_t)r * N + c]       = make_float2(acc[fm][fn][0], acc[fm][fn][1]);
                *(float2*)&Cf[(size_t)(r + 8) * N + c] = make_float2(acc[fm][fn][2], acc[fm][fn][3]);
            }
        }
        return;
    }

    // Fused QKV epilogue.
    bool isV = (bn >= 3072);
    float* rs = (float*)gsm;   // [4][128] row sum-of-squares partials
    int wg = warp >> 1;

    if (!isV) {
        #pragma unroll
        for (int fm = 0; fm < 4; fm++) {
            float p1 = 0.f, p2 = 0.f;
            #pragma unroll
            for (int fn = 0; fn < 8; fn++) {
                p1 += acc[fm][fn][0] * acc[fm][fn][0] + acc[fm][fn][1] * acc[fm][fn][1];
                p2 += acc[fm][fn][2] * acc[fm][fn][2] + acc[fm][fn][3] * acc[fm][fn][3];
            }
            p1 += __shfl_xor_sync(0xffffffffu, p1, 1);
            p1 += __shfl_xor_sync(0xffffffffu, p1, 2);
            p2 += __shfl_xor_sync(0xffffffffu, p2, 1);
            p2 += __shfl_xor_sync(0xffffffffu, p2, 2);
            if (ql == 0) {
                rs[wg * 128 + wm + fm * 16 + qr]     = p1;
                rs[wg * 128 + wm + fm * 16 + qr + 8] = p2;
            }
        }
        __syncthreads();
    }

    __half* Hb; int ldc, cofs; const float* gam; float sc;
    if (bn < 2048)      { Hb = Hq; ldc = 2048; cofs = bn;        gam = qg; sc = qscale; }
    else if (bn < 3072) { Hb = Hk; ldc = 1024; cofs = bn - 2048; gam = kg; sc = 1.0f; }
    else                { Hb = Hv; ldc = 1024; cofs = bn - 3072; gam = nullptr; sc = 0.f; }

    #pragma unroll
    for (int fm = 0; fm < 4; fm++) {
        int rb1 = wm + fm * 16 + qr;
        int rb2 = rb1 + 8;
        int rg1 = bm + rb1, rg2 = bm + rb2;
        if (isV) {
            #pragma unroll
            for (int fn = 0; fn < 8; fn++) {
                int c = cofs + wn + fn * 8 + ql * 2;
                *(uint32_t*)&Hb[(size_t)rg1 * ldc + c] = pack2(acc[fm][fn][0], acc[fm][fn][1]);
                *(uint32_t*)&Hb[(size_t)rg2 * ldc + c] = pack2(acc[fm][fn][2], acc[fm][fn][3]);
            }
        } else {
            float tot1 = rs[wg * 128 + rb1] + rs[(wg ^ 1) * 128 + rb1];
            float tot2 = rs[wg * 128 + rb2] + rs[(wg ^ 1) * 128 + rb2];
            float inv1 = rsqrtf(tot1 * (1.0f / HD_) + 1e-6f);
            float inv2 = rsqrtf(tot2 * (1.0f / HD_) + 1e-6f);
            int t1 = rg1 & (T_ - 1), t2 = rg2 & (T_ - 1);
            #pragma unroll
            for (int fn = 0; fn < 8; fn++) {
                int c  = cofs + wn + fn * 8 + ql * 2;
                int cc = c & 127;
                float g0 = gam[cc], g1 = gam[cc + 1];
                float c1 = cosT[t1 * HD_ + cc], s1 = sinT[t1 * HD_ + cc];
                float c2 = cosT[t2 * HD_ + cc], s2 = sinT[t2 * HD_ + cc];
                float h0 = acc[fm][fn][0] * inv1 * g0;
                float h1 = acc[fm][fn][1] * inv1 * g1;
                *(uint32_t*)&Hb[(size_t)rg1 * ldc + c] =
                    pack2((h0 * c1 - h1 * s1) * sc, (h1 * c1 + h0 * s1) * sc);
                h0 = acc[fm][fn][2] * inv2 * g0;
                h1 = acc[fm][fn][3] * inv2 * g1;
                *(uint32_t*)&Hb[(size_t)rg2 * ldc + c] =
                    pack2((h0 * c2 - h1 * s2) * sc, (h1 * c2 + h0 * s2) * sc);
            }
        }
    }
}

// ---------------------------------------------------------------------------
// FP16 flash attention: 64 q-rows/CTA, 128 threads = 4 warps (16 rows each),
// 2 CTAs/SM, spill-free (~170 regs). 64-wide K/V tiles cp.async
// double-buffered, m16n8k16 QK^T/PV, ldmatrix frags, P in registers,
// exp2-domain softmax with conditional O-rescale.
// ---------------------------------------------------------------------------
#define AQ_ST 136
#define KBUF (64 * AQ_ST)
#define VBUF (64 * AQ_ST)
#define ATTN_SMEM ((64*AQ_ST + 2*KBUF + 2*VBUF) * 2)   // 87040 B -> 2 CTA/SM

__global__ __launch_bounds__(128, 2)
void attn_f16(const __half* __restrict__ qh, const __half* __restrict__ kh,
              const __half* __restrict__ vr, __half* __restrict__ oh)
{
    extern __shared__ __half hsm[];
    __half* qs = hsm;                       // 64 x 136
    __half* ks = qs + 64 * AQ_ST;           // 2 x (64 x 136)
    __half* vs = ks + 2 * KBUF;             // 2 x (64 x 136), row-major [s][hd]

    int b = blockIdx.z, h = blockIdx.y;
    int kvh = h / G_;
    int t0 = blockIdx.x * 64;
    int tid = threadIdx.x, lane = tid & 31, warp = tid >> 5;
    int qr = lane >> 2;
    int ql = lane & 3;
    int row_off = lane & 15;
    int col_off = (lane >> 4) << 3;
    int r0w = warp * 16;

    const __half* kbase = kh + ((size_t)(b * T_) * KV_ + kvh) * HD_;
    const __half* vbase = vr + ((size_t)(b * T_) * KV_ + kvh) * HD_;

    // Stage Q (64x128) + K/V tile 0.  (128 threads, 8 cp16 each per tile)
    #pragma unroll
    for (int p = 0; p < 8; p++) {
        int slot = p * 128 + tid;
        int row = slot >> 4, c8 = (slot & 15) << 3;
        cp16(smem_u32(&qs[row * AQ_ST + c8]),
             &qh[((size_t)(b * T_ + t0 + row) * H_ + h) * HD_ + c8]);
    }
    #pragma unroll
    for (int p = 0; p < 8; p++) {
        int slot = p * 128 + tid;
        int row = slot >> 4, c8 = (slot & 15) << 3;
        cp16(smem_u32(&ks[row * AQ_ST + c8]), &kbase[(size_t)row * (KV_ * HD_) + c8]);
    }
    #pragma unroll
    for (int p = 0; p < 8; p++) {
        int slot = p * 128 + tid;
        int row = slot >> 4, c8 = (slot & 15) << 3;
        cp16(smem_u32(&vs[row * AQ_ST + c8]), &vbase[(size_t)row * (KV_ * HD_) + c8]);
    }
    CP_COMMIT();

    float m1 = -1e30f, m2 = -1e30f, l1 = 0.f, l2 = 0.f;
    float oa[16][4] = {};
    uint32_t qs_base = smem_u32(qs);

    const int NT = T_ / 64;
    for (int kt = 0; kt < NT; kt++) {
        int buf = kt & 1;
        if (kt + 1 < NT) {
            int nxt = buf ^ 1;
            int s0g = (kt + 1) * 64;
            #pragma unroll
            for (int p = 0; p < 8; p++) {
                int slot = p * 128 + tid;
                int row = slot >> 4, c8 = (slot & 15) << 3;
                cp16(smem_u32(&ks[nxt * KBUF + row * AQ_ST + c8]),
                     &kbase[(size_t)(s0g + row) * (KV_ * HD_) + c8]);
            }
            #pragma unroll
            for (int p = 0; p < 8; p++) {
                int slot = p * 128 + tid;
                int row = slot >> 4, c8 = (slot & 15) << 3;
                cp16(smem_u32(&vs[nxt * VBUF + row * AQ_ST + c8]),
                     &vbase[(size_t)(s0g + row) * (KV_ * HD_) + c8]);
            }
        }
        CP_COMMIT();
        CP_WAIT1();
        __syncthreads();

        uint32_t ks_base = smem_u32(ks + buf * KBUF);
        uint32_t vs_base = smem_u32(vs + buf * VBUF);

        // S = Q @ K^T : 8 k16 steps over HD=128, 8 n-frags over 64 cols.
        float s[8][4] = {};
        #pragma unroll
        for (int j = 0; j < 8; j++) {
            int kc = j * 16;
            uint32_t aq[4];
            ldsm_x4(aq, qs_base + (((r0w + row_off) * AQ_ST) + kc + col_off) * 2);
            uint32_t kb[4][4];
            #pragma unroll
            for (int i = 0; i < 4; i++)
                ldsm_x4(kb[i],
                        ks_base + (((i * 16 + row_off) * AQ_ST) + kc + col_off) * 2);
            #pragma unroll
            for (int nf = 0; nf < 8; nf++) {
                uint32_t b0 = kb[nf >> 1][nf & 1];
                uint32_t b1 = kb[nf >> 1][2 + (nf & 1)];
                mma_f16(s[nf], aq[0], aq[1], aq[2], aq[3], b0, b1);
            }
        }

        // Online softmax (exp2 domain); P packed into registers in PV A-layout.
        float rm1 = -1e30f, rm2 = -1e30f;
        #pragma unroll
        for (int nf = 0; nf < 8; nf++) {
            rm1 = fmaxf(rm1, fmaxf(s[nf][0], s[nf][1]));
            rm2 = fmaxf(rm2, fmaxf(s[nf][2], s[nf][3]));
        }
        #pragma unroll
        for (int off = 1; off <= 2; off <<= 1) {
            rm1 = fmaxf(rm1, __shfl_xor_sync(0xffffffffu, rm1, off));
            rm2 = fmaxf(rm2, __shfl_xor_sync(0xffffffffu, rm2, off));
        }
        float m1o = m1, m2o = m2;
        float nm1 = fmaxf(m1o, rm1), nm2 = fmaxf(m2o, rm2);
        float rs1 = 0.f, rs2 = 0.f;
        uint32_t pp[8], pq[8];
        #pragma unroll
        for (int nf = 0; nf < 8; nf++) {
            float p0 = ex2(s[nf][0] - nm1);
            float p1 = ex2(s[nf][1] - nm1);
            float p2 = ex2(s[nf][2] - nm2);
            float p3 = ex2(s[nf][3] - nm2);
            rs1 += p0 + p1; rs2 += p2 + p3;
            pp[nf] = pack2(p0, p1);
            pq[nf] = pack2(p2, p3);
        }
        #pragma unroll
        for (int off = 1; off <= 2; off <<= 1) {
            rs1 += __shfl_xor_sync(0xffffffffu, rs1, off);
            rs2 += __shfl_xor_sync(0xffffffffu, rs2, off);
        }
        float corr1 = ex2(m1o - nm1), corr2 = ex2(m2o - nm2);
        l1 = l1 * corr1 + rs1; m1 = nm1;
        l2 = l2 * corr2 + rs2; m2 = nm2;
        if (nm1 > m1o || nm2 > m2o) {
            #pragma unroll
            for (int nf = 0; nf < 16; nf++) {
                oa[nf][0] *= corr1; oa[nf][1] *= corr1;
                oa[nf][2] *= corr2; oa[nf][3] *= corr2;
            }
        }

        // O += P @ V : 4 k16 steps over s=64, 16 n-frags over hd=128.
        #pragma unroll
        for (int j = 0; j < 4; j++) {
            int kc = j * 16;
            uint32_t vb[8][4];
            #pragma unroll
            for (int i = 0; i < 8; i++)
                ldsm_x4_t(vb[i],
                          vs_base + (((kc + row_off) * AQ_ST) + i * 16 + col_off) * 2);
            #pragma unroll
            for (int nf = 0; nf < 16; nf++) {
                uint32_t b0 = vb[nf >> 1][2 * (nf & 1)];
                uint32_t b1 = vb[nf >> 1][2 * (nf & 1) + 1];
                mma_f16(oa[nf], pp[2 * j], pq[2 * j], pp[2 * j + 1], pq[2 * j + 1], b0, b1);
            }
        }
        __syncthreads();  // compute done before next iter's cp.async overwrites
    }

    float inv1 = 1.0f / l1, inv2 = 1.0f / l2;
    int rr = r0w + qr;
    size_t base1 = ((size_t)(b * T_ + t0 + rr) * H_ + h) * HD_;
    size_t base2 = ((size_t)(b * T_ + t0 + rr + 8) * H_ + h) * HD_;
    #pragma unroll
    for (int nf = 0; nf < 16; nf++) {
        int c = nf * 8 + ql * 2;
        *(uint32_t*)&oh[base1 + c] = pack2(oa[nf][0] * inv1, oa[nf][1] * inv1);
        *(uint32_t*)&oh[base2 + c] = pack2(oa[nf][2] * inv2, oa[nf][3] * inv2);
    }
}

// ---------------------------------------------------------------------------
// Launch
// ---------------------------------------------------------------------------
extern "C" void kernel_launch(void* const* d_in, const int* in_sizes, int n_in,
                              void* d_out, int out_size)
{
    const float* x    = (const float*)d_in[0];
    const float* cosT = (const float*)d_in[1];
    const float* sinT = (const float*)d_in[2];
    const float* Wq   = (const float*)d_in[3];
    const float* Wk   = (const float*)d_in[4];
    const float* Wv   = (const float*)d_in[5];
    const float* Wo   = (const float*)d_in[6];
    const float* qg   = (const float*)d_in[7];
    const float* kg   = (const float*)d_in[8];

    __half *xh, *qh, *kh, *vr, *oh, *wt;
    cudaGetSymbolAddress((void**)&xh, g_xh);
    cudaGetSymbolAddress((void**)&qh, g_qh);
    cudaGetSymbolAddress((void**)&kh, g_kh);
    cudaGetSymbolAddress((void**)&vr, g_vr);
    cudaGetSymbolAddress((void**)&oh, g_oh);
    cudaGetSymbolAddress((void**)&wt, g_wt);

    __half* WqkvT = wt;                      // [4096][2048]
    __half* WoT   = wt + 8 * 1024 * 1024;    // [2048][2048]

    const int M = B_ * T_;  // 8192

    transpose_all<<<dim3(64, 64, 4), 256>>>(Wq, Wk, Wv, Wo, wt);
    cvt_half<<<(M * DM_) / (256 * 8), 256>>>(x, xh);

    const float qscale = 0.0883883476483184405f * 1.4426950408889634f;

    cudaFuncSetAttribute(gemm_f16h, cudaFuncAttributeMaxDynamicSharedMemorySize, GEMM_SMEM);
    gemm_f16h<<<dim3(4096/256, M/128), 256, GEMM_SMEM>>>(
        xh, WqkvT, nullptr, qh, kh, vr, qg, kg, cosT, sinT, qscale, M, 4096, DM_);

    cudaFuncSetAttribute(attn_f16, cudaFuncAttributeMaxDynamicSharedMemorySize, ATTN_SMEM);
    attn_f16<<<dim3(T_ / 64, H_, B_), 128, ATTN_SMEM>>>(qh, kh, vr, oh);

    gemm_f16h<<<dim3(DM_/256, M/128), 256, GEMM_SMEM>>>(
        oh, WoT, (float*)d_out, nullptr, nullptr, nullptr,
        nullptr, nullptr, nullptr, nullptr, 0.f, M, DM_, DM_);
}

// round 17
// speedup vs baseline: 1.0521x; 1.0332x over previous
#include <cuda_runtime.h>
#include <cuda_fp16.h>
#include <math.h>
#include <stdint.h>

#define B_ 4
#define T_ 2048
#define DM_ 2048
#define H_ 16
#define KV_ 8
#define HD_ 128
#define G_ 2

// Scratch (no allocations allowed) — static device globals.
__device__ __half g_xh[B_*T_*DM_];
__device__ __half g_qh[B_*T_*H_*HD_];
__device__ __half g_kh[B_*T_*KV_*HD_];
__device__ __half g_vr[B_*T_*KV_*HD_];
__device__ __half g_oh[B_*T_*H_*HD_];
__device__ __half g_wt[12*1024*1024];   // WqkvT [4096][2048], WoT [2048][2048]

// ---------------------------------------------------------------------------
// Helpers
// ---------------------------------------------------------------------------
__device__ __forceinline__ uint32_t h2u(__half2 h) { return *(uint32_t*)&h; }
__device__ __forceinline__ uint32_t pack2(float lo, float hi) {
    return h2u(__floats2half2_rn(lo, hi));
}
__device__ __forceinline__ float ex2(float x) {
    float r;
    asm("ex2.approx.f32 %0, %1;" : "=f"(r) : "f"(x));
    return r;
}

__device__ __forceinline__ void mma_f16(float c[4],
                                        uint32_t a0, uint32_t a1, uint32_t a2, uint32_t a3,
                                        uint32_t b0, uint32_t b1) {
    asm volatile(
        "mma.sync.aligned.m16n8k16.row.col.f32.f16.f16.f32 "
        "{%0,%1,%2,%3}, {%4,%5,%6,%7}, {%8,%9}, {%0,%1,%2,%3};"
        : "+f"(c[0]), "+f"(c[1]), "+f"(c[2]), "+f"(c[3])
        : "r"(a0), "r"(a1), "r"(a2), "r"(a3), "r"(b0), "r"(b1));
}

// ldmatrix x4 (non-trans): A-frags / B-frags from [row][k] tiles.
__device__ __forceinline__ void ldsm_x4(uint32_t* d, uint32_t addr) {
    asm volatile("ldmatrix.sync.aligned.m8n8.x4.shared.b16 {%0,%1,%2,%3}, [%4];"
                 : "=r"(d[0]), "=r"(d[1]), "=r"(d[2]), "=r"(d[3]) : "r"(addr));
}
// ldmatrix x4 trans: B-frags (Vᵀ) from row-major [k(s)][n(hd)] tiles.
__device__ __forceinline__ void ldsm_x4_t(uint32_t* d, uint32_t addr) {
    asm volatile("ldmatrix.sync.aligned.m8n8.x4.trans.shared.b16 {%0,%1,%2,%3}, [%4];"
                 : "=r"(d[0]), "=r"(d[1]), "=r"(d[2]), "=r"(d[3]) : "r"(addr));
}

__device__ __forceinline__ uint32_t smem_u32(const void* p) {
    uint32_t a;
    asm("{ .reg .u64 t; cvta.to.shared.u64 t, %1; cvt.u32.u64 %0, t; }" : "=r"(a) : "l"(p));
    return a;
}
__device__ __forceinline__ void cp16(uint32_t s, const void* g) {
    asm volatile("cp.async.ca.shared.global [%0], [%1], 16;" :: "r"(s), "l"(g));
}
#define CP_COMMIT() asm volatile("cp.async.commit_group;")
#define CP_WAIT1()  asm volatile("cp.async.wait_group 1;")

// ---------------------------------------------------------------------------
// All four weight transposes (fp32 -> fp16, W[K][N] -> WT[N][K]) in ONE launch.
// ---------------------------------------------------------------------------
__global__ void transpose_all(const float* __restrict__ Wq, const float* __restrict__ Wk,
                              const float* __restrict__ Wv, const float* __restrict__ Wo,
                              __half* __restrict__ WT)
{
    __shared__ float t[32][33];
    int z = blockIdx.z;
    const float* W; __half* dst; int N;
    if (z == 0)      { W = Wq; N = 2048; dst = WT; }
    else if (z == 1) { W = Wk; N = 1024; dst = WT + 2048ull * 2048; }
    else if (z == 2) { W = Wv; N = 1024; dst = WT + 3072ull * 2048; }
    else             { W = Wo; N = 2048; dst = WT + 8ull * 1024 * 1024; }
    int n0 = blockIdx.x * 32, k0 = blockIdx.y * 32;
    if (n0 >= N) return;
    const int K = 2048;
    int tx = threadIdx.x & 31, ty = threadIdx.x >> 5;
    #pragma unroll
    for (int j = 0; j < 4; j++)
        t[ty + 8 * j][tx] = W[(size_t)(k0 + ty + 8 * j) * N + n0 + tx];
    __syncthreads();
    #pragma unroll
    for (int j = 0; j < 4; j++)
        dst[(size_t)(n0 + ty + 8 * j) * K + k0 + tx] = __float2half_rn(t[tx][ty + 8 * j]);
}

// fp32 -> fp16 bulk convert (8 elements/thread).
__global__ void cvt_half(const float* __restrict__ in, __half* __restrict__ out)
{
    size_t i = ((size_t)blockIdx.x * blockDim.x + threadIdx.x) * 8;
    float4 a = *(const float4*)&in[i];
    float4 b = *(const float4*)&in[i + 4];
    *(uint4*)&out[i] = make_uint4(pack2(a.x, a.y), pack2(a.z, a.w),
                                  pack2(b.x, b.y), pack2(b.z, b.w));
}

// ---------------------------------------------------------------------------
// All-fp16 pipelined GEMM: block 128x256, BK=64, cp.async 2-stage,
// 256 threads = 8 warps (2m x 4n of 64x64 tiles), m16n8k16, ldmatrix frags.
//   Cf != null : plain fp32 store (Wo GEMM).
//   else       : fused QKV — RMSNorm+RoPE on q/k, plain fp16 store for v.
// ---------------------------------------------------------------------------
#define GST 72
#define GT_A (128 * GST)
#define GT_B (256 * GST)
#define GEMM_SMEM ((2 * (GT_A + GT_B)) * 2)   // 110592 bytes

__global__ __launch_bounds__(256, 1)
void gemm_f16h(const __half* __restrict__ A, const __half* __restrict__ WT,
               float* __restrict__ Cf,
               __half* __restrict__ Hq, __half* __restrict__ Hk, __half* __restrict__ Hv,
               const float* __restrict__ qg, const float* __restrict__ kg,
               const float* __restrict__ cosT, const float* __restrict__ sinT,
               float qscale, int M, int N, int K)
{
    extern __shared__ __half gsm[];
    __half* As[2] = { gsm, gsm + GT_A };
    __half* Bs[2] = { gsm + 2 * GT_A, gsm + 2 * GT_A + GT_B };

    int tid  = threadIdx.x;
    int lane = tid & 31;
    int warp = tid >> 5;
    int qr = lane >> 2, ql = lane & 3;
    int row_off = lane & 15;
    int col_off = (lane >> 4) << 3;
    int wm = (warp & 1) * 64;
    int wn = (warp >> 1) * 64;
    int bm = blockIdx.y * 128, bn = blockIdx.x * 256;

    float acc[4][8][4] = {};
    const int NT = K / 64;

    #pragma unroll
    for (int p = 0; p < 4; p++) {
        int slot = p * 256 + tid;
        int r = slot >> 3, c8 = (slot & 7) << 3;
        cp16(smem_u32(&As[0][r * GST + c8]), &A[(size_t)(bm + r) * K + c8]);
    }
    #pragma unroll
    for (int p = 0; p < 8; p++) {
        int slot = p * 256 + tid;
        int r = slot >> 3, c8 = (slot & 7) << 3;
        cp16(smem_u32(&Bs[0][r * GST + c8]), &WT[(size_t)(bn + r) * K + c8]);
    }
    CP_COMMIT();

    for (int kt = 0; kt < NT; kt++) {
        int buf = kt & 1;
        if (kt + 1 < NT) {
            int nxt = buf ^ 1;
            int k0 = (kt + 1) * 64;
            #pragma unroll
            for (int p = 0; p < 4; p++) {
                int slot = p * 256 + tid;
                int r = slot >> 3, c8 = (slot & 7) << 3;
                cp16(smem_u32(&As[nxt][r * GST + c8]), &A[(size_t)(bm + r) * K + k0 + c8]);
            }
            #pragma unroll
            for (int p = 0; p < 8; p++) {
                int slot = p * 256 + tid;
                int r = slot >> 3, c8 = (slot & 7) << 3;
                cp16(smem_u32(&Bs[nxt][r * GST + c8]), &WT[(size_t)(bn + r) * K + k0 + c8]);
            }
        }
        CP_COMMIT();
        CP_WAIT1();
        __syncthreads();

        uint32_t a_base = smem_u32(As[buf]);
        uint32_t b_base = smem_u32(Bs[buf]);
        #pragma unroll
        for (int ks = 0; ks < 4; ks++) {
            int kc = ks * 16;
            uint32_t af[4][4];
            #pragma unroll
            for (int fm = 0; fm < 4; fm++)
                ldsm_x4(af[fm],
                        a_base + (((wm + fm * 16 + row_off) * GST) + kc + col_off) * 2);
            uint32_t bf[4][4];
            #pragma unroll
            for (int i = 0; i < 4; i++)
                ldsm_x4(bf[i],
                        b_base + (((wn + i * 16 + row_off) * GST) + kc + col_off) * 2);
            #pragma unroll
            for (int fn = 0; fn < 8; fn++) {
                uint32_t b0 = bf[fn >> 1][fn & 1];
                uint32_t b1 = bf[fn >> 1][2 + (fn & 1)];
                #pragma unroll
                for (int fm = 0; fm < 4; fm++)
                    mma_f16(acc[fm][fn], af[fm][0], af[fm][1], af[fm][2], af[fm][3], b0, b1);
            }
        }
        __syncthreads();
    }

    if (Cf) {
        #pragma unroll
        for (int fm = 0; fm < 4; fm++) {
            #pragma unroll
            for (int fn = 0; fn < 8; fn++) {
                int r = bm + wm + fm * 16 + qr;
                int c = bn + wn + fn * 8 + ql * 2;
                *(float2*)&Cf[(size_t)r * N + c]       = make_float2(acc[fm][fn][0], acc[fm][fn][1]);
                *(float2*)&Cf[(size_t)(r + 8) * N + c] = make_float2(acc[fm][fn][2], acc[fm][fn][3]);
            }
        }
        return;
    }

    // Fused QKV epilogue.
    bool isV = (bn >= 3072);
    float* rs = (float*)gsm;   // [4][128] row sum-of-squares partials
    int wg = warp >> 1;

    if (!isV) {
        #pragma unroll
        for (int fm = 0; fm < 4; fm++) {
            float p1 = 0.f, p2 = 0.f;
            #pragma unroll
            for (int fn = 0; fn < 8; fn++) {
                p1 += acc[fm][fn][0] * acc[fm][fn][0] + acc[fm][fn][1] * acc[fm][fn][1];
                p2 += acc[fm][fn][2] * acc[fm][fn][2] + acc[fm][fn][3] * acc[fm][fn][3];
            }
            p1 += __shfl_xor_sync(0xffffffffu, p1, 1);
            p1 += __shfl_xor_sync(0xffffffffu, p1, 2);
            p2 += __shfl_xor_sync(0xffffffffu, p2, 1);
            p2 += __shfl_xor_sync(0xffffffffu, p2, 2);
            if (ql == 0) {
                rs[wg * 128 + wm + fm * 16 + qr]     = p1;
                rs[wg * 128 + wm + fm * 16 + qr + 8] = p2;
            }
        }
        __syncthreads();
    }

    __half* Hb; int ldc, cofs; const float* gam; float sc;
    if (bn < 2048)      { Hb = Hq; ldc = 2048; cofs = bn;        gam = qg; sc = qscale; }
    else if (bn < 3072) { Hb = Hk; ldc = 1024; cofs = bn - 2048; gam = kg; sc = 1.0f; }
    else                { Hb = Hv; ldc = 1024; cofs = bn - 3072; gam = nullptr; sc = 0.f; }

    #pragma unroll
    for (int fm = 0; fm < 4; fm++) {
        int rb1 = wm + fm * 16 + qr;
        int rb2 = rb1 + 8;
        int rg1 = bm + rb1, rg2 = bm + rb2;
        if (isV) {
            #pragma unroll
            for (int fn = 0; fn < 8; fn++) {
                int c = cofs + wn + fn * 8 + ql * 2;
                *(uint32_t*)&Hb[(size_t)rg1 * ldc + c] = pack2(acc[fm][fn][0], acc[fm][fn][1]);
                *(uint32_t*)&Hb[(size_t)rg2 * ldc + c] = pack2(acc[fm][fn][2], acc[fm][fn][3]);
            }
        } else {
            float tot1 = rs[wg * 128 + rb1] + rs[(wg ^ 1) * 128 + rb1];
            float tot2 = rs[wg * 128 + rb2] + rs[(wg ^ 1) * 128 + rb2];
            float inv1 = rsqrtf(tot1 * (1.0f / HD_) + 1e-6f);
            float inv2 = rsqrtf(tot2 * (1.0f / HD_) + 1e-6f);
            int t1 = rg1 & (T_ - 1), t2 = rg2 & (T_ - 1);
            #pragma unroll
            for (int fn = 0; fn < 8; fn++) {
                int c  = cofs + wn + fn * 8 + ql * 2;
                int cc = c & 127;
                float g0 = gam[cc], g1 = gam[cc + 1];
                float c1 = cosT[t1 * HD_ + cc], s1 = sinT[t1 * HD_ + cc];
                float c2 = cosT[t2 * HD_ + cc], s2 = sinT[t2 * HD_ + cc];
                float h0 = acc[fm][fn][0] * inv1 * g0;
                float h1 = acc[fm][fn][1] * inv1 * g1;
                *(uint32_t*)&Hb[(size_t)rg1 * ldc + c] =
                    pack2((h0 * c1 - h1 * s1) * sc, (h1 * c1 + h0 * s1) * sc);
                h0 = acc[fm][fn][2] * inv2 * g0;
                h1 = acc[fm][fn][3] * inv2 * g1;
                *(uint32_t*)&Hb[(size_t)rg2 * ldc + c] =
                    pack2((h0 * c2 - h1 * s2) * sc, (h1 * c2 + h0 * s2) * sc);
            }
        }
    }
}

// ---------------------------------------------------------------------------
// FP16 flash attention: 128 q-rows/CTA, 128 threads = 4 warps (32 rows each),
// 2 CTAs/SM. Each K/V B-fragment feeds 2 row-frag MMAs (halves LDSM/MMA vs
// 16-row tiles) and NO V-prefetch double-buffer (keeps regs < 255, no spill).
// 64-wide K/V tiles cp.async double-buffered; m16n8k16 QK^T/PV; ldmatrix
// frags; P in registers; exp2-domain softmax with conditional O-rescale.
// ---------------------------------------------------------------------------
#define AQ_ST 136
#define KBUF (64 * AQ_ST)
#define VBUF (64 * AQ_ST)
#define ATTN_SMEM ((128*AQ_ST + 2*KBUF + 2*VBUF) * 2)   // 104448 B -> 2 CTA/SM

__global__ __launch_bounds__(128, 2)
void attn_f16(const __half* __restrict__ qh, const __half* __restrict__ kh,
              const __half* __restrict__ vr, __half* __restrict__ oh)
{
    extern __shared__ __half hsm[];
    __half* qs = hsm;                       // 128 x 136
    __half* ks = qs + 128 * AQ_ST;          // 2 x (64 x 136)
    __half* vs = ks + 2 * KBUF;             // 2 x (64 x 136), row-major [s][hd]

    int b = blockIdx.z, h = blockIdx.y;
    int kvh = h / G_;
    int t0 = blockIdx.x * 128;
    int tid = threadIdx.x, lane = tid & 31, warp = tid >> 5;
    int qr = lane >> 2;
    int ql = lane & 3;
    int row_off = lane & 15;
    int col_off = (lane >> 4) << 3;
    int r0w = warp * 32;

    const __half* kbase = kh + ((size_t)(b * T_) * KV_ + kvh) * HD_;
    const __half* vbase = vr + ((size_t)(b * T_) * KV_ + kvh) * HD_;

    #pragma unroll
    for (int p = 0; p < 16; p++) {
        int slot = p * 128 + tid;
        int row = slot >> 4, c8 = (slot & 15) << 3;
        cp16(smem_u32(&qs[row * AQ_ST + c8]),
             &qh[((size_t)(b * T_ + t0 + row) * H_ + h) * HD_ + c8]);
    }
    #pragma unroll
    for (int p = 0; p < 8; p++) {
        int slot = p * 128 + tid;
        int row = slot >> 4, c8 = (slot & 15) << 3;
        cp16(smem_u32(&ks[row * AQ_ST + c8]), &kbase[(size_t)row * (KV_ * HD_) + c8]);
    }
    #pragma unroll
    for (int p = 0; p < 8; p++) {
        int slot = p * 128 + tid;
        int row = slot >> 4, c8 = (slot & 15) << 3;
        cp16(smem_u32(&vs[row * AQ_ST + c8]), &vbase[(size_t)row * (KV_ * HD_) + c8]);
    }
    CP_COMMIT();

    float m[2][2] = {{-1e30f, -1e30f}, {-1e30f, -1e30f}};
    float l[2][2] = {};
    float oa[2][16][4] = {};
    uint32_t qs_base = smem_u32(qs);

    const int NT = T_ / 64;
    for (int kt = 0; kt < NT; kt++) {
        int buf = kt & 1;
        if (kt + 1 < NT) {
            int nxt = buf ^ 1;
            int s0g = (kt + 1) * 64;
            #pragma unroll
            for (int p = 0; p < 8; p++) {
                int slot = p * 128 + tid;
                int row = slot >> 4, c8 = (slot & 15) << 3;
                cp16(smem_u32(&ks[nxt * KBUF + row * AQ_ST + c8]),
                     &kbase[(size_t)(s0g + row) * (KV_ * HD_) + c8]);
            }
            #pragma unroll
            for (int p = 0; p < 8; p++) {
                int slot = p * 128 + tid;
                int row = slot >> 4, c8 = (slot & 15) << 3;
                cp16(smem_u32(&vs[nxt * VBUF + row * AQ_ST + c8]),
                     &vbase[(size_t)(s0g + row) * (KV_ * HD_) + c8]);
            }
        }
        CP_COMMIT();
        CP_WAIT1();
        __syncthreads();

        uint32_t ks_base = smem_u32(ks + buf * KBUF);
        uint32_t vs_base = smem_u32(vs + buf * VBUF);

        // S = Q @ K^T : 8 k16 steps over HD=128, 8 n-frags, 2 row-frags.
        float s[2][8][4] = {};
        #pragma unroll
        for (int j = 0; j < 8; j++) {
            int kc = j * 16;
            uint32_t aq[2][4];
            #pragma unroll
            for (int f = 0; f < 2; f++)
                ldsm_x4(aq[f],
                        qs_base + (((r0w + f * 16 + row_off) * AQ_ST) + kc + col_off) * 2);
            uint32_t kb[4][4];
            #pragma unroll
            for (int i = 0; i < 4; i++)
                ldsm_x4(kb[i],
                        ks_base + (((i * 16 + row_off) * AQ_ST) + kc + col_off) * 2);
            #pragma unroll
            for (int nf = 0; nf < 8; nf++) {
                uint32_t b0 = kb[nf >> 1][nf & 1];
                uint32_t b1 = kb[nf >> 1][2 + (nf & 1)];
                #pragma unroll
                for (int f = 0; f < 2; f++)
                    mma_f16(s[f][nf], aq[f][0], aq[f][1], aq[f][2], aq[f][3], b0, b1);
            }
        }

        // Online softmax (exp2 domain); P packed into registers in PV A-layout.
        uint32_t pp[2][8], pq[2][8];
        #pragma unroll
        for (int f = 0; f < 2; f++) {
            float rm1 = -1e30f, rm2 = -1e30f;
            #pragma unroll
            for (int nf = 0; nf < 8; nf++) {
                rm1 = fmaxf(rm1, fmaxf(s[f][nf][0], s[f][nf][1]));
                rm2 = fmaxf(rm2, fmaxf(s[f][nf][2], s[f][nf][3]));
            }
            #pragma unroll
            for (int off = 1; off <= 2; off <<= 1) {
                rm1 = fmaxf(rm1, __shfl_xor_sync(0xffffffffu, rm1, off));
                rm2 = fmaxf(rm2, __shfl_xor_sync(0xffffffffu, rm2, off));
            }
            float m1o = m[f][0], m2o = m[f][1];
            float nm1 = fmaxf(m1o, rm1), nm2 = fmaxf(m2o, rm2);
            float rs1 = 0.f, rs2 = 0.f;
            #pragma unroll
            for (int nf = 0; nf < 8; nf++) {
                float p0 = ex2(s[f][nf][0] - nm1);
                float p1 = ex2(s[f][nf][1] - nm1);
                float p2 = ex2(s[f][nf][2] - nm2);
                float p3 = ex2(s[f][nf][3] - nm2);
                rs1 += p0 + p1; rs2 += p2 + p3;
                pp[f][nf] = pack2(p0, p1);
                pq[f][nf] = pack2(p2, p3);
            }
            #pragma unroll
            for (int off = 1; off <= 2; off <<= 1) {
                rs1 += __shfl_xor_sync(0xffffffffu, rs1, off);
                rs2 += __shfl_xor_sync(0xffffffffu, rs2, off);
            }
            float corr1 = ex2(m1o - nm1), corr2 = ex2(m2o - nm2);
            l[f][0] = l[f][0] * corr1 + rs1; m[f][0] = nm1;
            l[f][1] = l[f][1] * corr2 + rs2; m[f][1] = nm2;
            if (nm1 > m1o || nm2 > m2o) {
                #pragma unroll
                for (int nf = 0; nf < 16; nf++) {
                    oa[f][nf][0] *= corr1; oa[f][nf][1] *= corr1;
                    oa[f][nf][2] *= corr2; oa[f][nf][3] *= corr2;
                }
            }
        }

        // O += P @ V : 4 k16 steps over s=64, 16 n-frags over hd=128.
        // V B-frags loaded in-loop (no prefetch double-buffer -> no spills);
        // each vb feeds both row-frags.
        #pragma unroll
        for (int j = 0; j < 4; j++) {
            int kc = j * 16;
            uint32_t vb[8][4];
            #pragma unroll
            for (int i = 0; i < 8; i++)
                ldsm_x4_t(vb[i],
                          vs_base + (((kc + row_off) * AQ_ST) + i * 16 + col_off) * 2);
            #pragma unroll
            for (int nf = 0; nf < 16; nf++) {
                uint32_t b0 = vb[nf >> 1][2 * (nf & 1)];
                uint32_t b1 = vb[nf >> 1][2 * (nf & 1) + 1];
                #pragma unroll
                for (int f = 0; f < 2; f++)
                    mma_f16(oa[f][nf], pp[f][2 * j], pq[f][2 * j],
                            pp[f][2 * j + 1], pq[f][2 * j + 1], b0, b1);
            }
        }
        __syncthreads();  // compute done before next iter's cp.async overwrites
    }

    #pragma unroll
    for (int f = 0; f < 2; f++) {
        float inv1 = 1.0f / l[f][0], inv2 = 1.0f / l[f][1];
        int rr = r0w + f * 16 + qr;
        size_t base1 = ((size_t)(b * T_ + t0 + rr) * H_ + h) * HD_;
        size_t base2 = ((size_t)(b * T_ + t0 + rr + 8) * H_ + h) * HD_;
        #pragma unroll
        for (int nf = 0; nf < 16; nf++) {
            int c = nf * 8 + ql * 2;
            *(uint32_t*)&oh[base1 + c] = pack2(oa[f][nf][0] * inv1, oa[f][nf][1] * inv1);
            *(uint32_t*)&oh[base2 + c] = pack2(oa[f][nf][2] * inv2, oa[f][nf][3] * inv2);
        }
    }
}

// ---------------------------------------------------------------------------
// Launch
// ---------------------------------------------------------------------------
extern "C" void kernel_launch(void* const* d_in, const int* in_sizes, int n_in,
                              void* d_out, int out_size)
{
    const float* x    = (const float*)d_in[0];
    const float* cosT = (const float*)d_in[1];
    const float* sinT = (const float*)d_in[2];
    const float* Wq   = (const float*)d_in[3];
    const float* Wk   = (const float*)d_in[4];
    const float* Wv   = (const float*)d_in[5];
    const float* Wo   = (const float*)d_in[6];
    const float* qg   = (const float*)d_in[7];
    const float* kg   = (const float*)d_in[8];

    __half *xh, *qh, *kh, *vr, *oh, *wt;
    cudaGetSymbolAddress((void**)&xh, g_xh);
    cudaGetSymbolAddress((void**)&qh, g_qh);
    cudaGetSymbolAddress((void**)&kh, g_kh);
    cudaGetSymbolAddress((void**)&vr, g_vr);
    cudaGetSymbolAddress((void**)&oh, g_oh);
    cudaGetSymbolAddress((void**)&wt, g_wt);

    __half* WqkvT = wt;                      // [4096][2048]
    __half* WoT   = wt + 8 * 1024 * 1024;    // [2048][2048]

    const int M = B_ * T_;  // 8192

    transpose_all<<<dim3(64, 64, 4), 256>>>(Wq, Wk, Wv, Wo, wt);
    cvt_half<<<(M * DM_) / (256 * 8), 256>>>(x, xh);

    const float qscale = 0.0883883476483184405f * 1.4426950408889634f;

    cudaFuncSetAttribute(gemm_f16h, cudaFuncAttributeMaxDynamicSharedMemorySize, GEMM_SMEM);
    gemm_f16h<<<dim3(4096/256, M/128), 256, GEMM_SMEM>>>(
        xh, WqkvT, nullptr, qh, kh, vr, qg, kg, cosT, sinT, qscale, M, 4096, DM_);

    cudaFuncSetAttribute(attn_f16, cudaFuncAttributeMaxDynamicSharedMemorySize, ATTN_SMEM);
    attn_f16<<<dim3(T_ / 128, H_, B_), 128, ATTN_SMEM>>>(qh, kh, vr, oh);

    gemm_f16h<<<dim3(DM_/256, M/128), 256, GEMM_SMEM>>>(
        oh, WoT, (float*)d_out, nullptr, nullptr, nullptr,
        nullptr, nullptr, nullptr, nullptr, 0.f, M, DM_, DM_);
}